// round 7
// baseline (speedup 1.0000x reference)
#include <cuda_runtime.h>
#include <math.h>

#define NLOC 8192
#define SEQ 32
#define CDIM 128
#define NHEAD 8
#define HD 16
#define MROWS (NLOC*SEQ)   // 262144
#define FFND 512

// -------- scratch (static device globals; no runtime allocation) --------
__device__ float g_x1[(size_t)MROWS * CDIM];  // 128 MB
__device__ float g_h[(size_t)MROWS * FFND];   // 512 MB

// ======================= mma / cp.async helpers =======================
__device__ __forceinline__ void mma8(float* c, const float* a, const float* b) {
    asm volatile(
        "mma.sync.aligned.m16n8k8.row.col.f32.tf32.tf32.f32 "
        "{%0,%1,%2,%3}, {%4,%5,%6,%7}, {%8,%9}, {%0,%1,%2,%3};"
        : "+f"(c[0]), "+f"(c[1]), "+f"(c[2]), "+f"(c[3])
        : "r"(__float_as_uint(a[0])), "r"(__float_as_uint(a[1])),
          "r"(__float_as_uint(a[2])), "r"(__float_as_uint(a[3])),
          "r"(__float_as_uint(b[0])), "r"(__float_as_uint(b[1])));
}

__device__ __forceinline__ void cp16(void* s, const void* g) {
    unsigned saddr = (unsigned)__cvta_generic_to_shared(s);
    asm volatile("cp.async.cg.shared.global [%0], [%1], 16;" :: "r"(saddr), "l"(g));
}
__device__ __forceinline__ void cp_commit() {
    asm volatile("cp.async.commit_group;");
}
template<int N>
__device__ __forceinline__ void cp_wait() {
    asm volatile("cp.async.wait_group %0;" :: "n"(N));
}

// packed f32x2
typedef unsigned long long u64t;
__device__ __forceinline__ u64t pk2(float lo, float hi) {
    u64t r; asm("mov.b64 %0,{%1,%2};" : "=l"(r) : "f"(lo), "f"(hi)); return r;
}
__device__ __forceinline__ void upk2(u64t v, float& lo, float& hi) {
    asm("mov.b64 {%0,%1},%2;" : "=f"(lo), "=f"(hi) : "l"(v));
}
__device__ __forceinline__ void fma2(u64t& d, u64t a, u64t b) {
    asm("fma.rn.f32x2 %0,%1,%2,%0;" : "+l"(d) : "l"(a), "l"(b));
}

// ================== 256-thread GEMM machinery (FFN kernels) ==================
// CTA tile 128x128, 8 warps, warp tile 64x32, K chunk 32, 3-stage cp.async.
#define AP 36
#define BP 136
#define ASZ (128*AP)
#define BSZ (32*BP)
#define BUFSZ (ASZ+BSZ)          // 8960 floats per stage
#define G3_SMEM_FLOATS (3*BUFSZ) // 26880 floats
#define G3_SMEM_BYTES (G3_SMEM_FLOATS*4)   // 107520 B

__device__ __forceinline__ void copy_chunk_256(
    const float* __restrict__ A, size_t lda, int m0,
    const float* __restrict__ B, int ldb, int k0,
    float* As, float* Bs, int tid)
{
    const int ia = tid >> 3;            // 0..31
    const int kc = (tid & 7) * 4;       // 0..28
#pragma unroll
    for (int p = 0; p < 4; p++)
        cp16(&As[(ia + 32 * p) * AP + kc],
             &A[(size_t)(m0 + ia + 32 * p) * lda + k0 + kc]);
    const int nb = (tid & 7) * 4;
#pragma unroll
    for (int p = 0; p < 4; p++)
        cp16(&Bs[ia * BP + nb + 32 * p],
             &B[(size_t)(k0 + ia) * ldb + nb + 32 * p]);
    cp_commit();
}

__device__ __forceinline__ void compute_chunk(
    const float* __restrict__ As, const float* __restrict__ Bs,
    float acc[4][4][4], int wm, int wn, int g, int t)
{
#pragma unroll
    for (int ks = 0; ks < 4; ks++) {
        const int kk = ks * 8;
        float b[4][2];
#pragma unroll
        for (int nf = 0; nf < 4; nf++) {
            const int n = wn * 32 + nf * 8 + g;
            b[nf][0] = Bs[(kk + t) * BP + n];
            b[nf][1] = Bs[(kk + t + 4) * BP + n];
        }
#pragma unroll
        for (int mf = 0; mf < 4; mf++) {
            const int row = wm * 64 + mf * 16 + g;
            float a[4];
            a[0] = As[row * AP + kk + t];
            a[1] = As[(row + 8) * AP + kk + t];
            a[2] = As[row * AP + kk + t + 4];
            a[3] = As[(row + 8) * AP + kk + t + 4];
#pragma unroll
            for (int nf = 0; nf < 4; nf++)
                mma8(acc[mf][nf], a, b[nf]);
        }
    }
}

template<int NC>
__device__ __forceinline__ void run_gemm(
    const float* __restrict__ A, size_t lda, int m0,
    const float* __restrict__ B, int ldb,
    float acc[4][4][4], float* smem, int tid,
    int wm, int wn, int g, int t)
{
#pragma unroll
    for (int i = 0; i < 4; i++)
#pragma unroll
        for (int j = 0; j < 4; j++)
#pragma unroll
            for (int q = 0; q < 4; q++) acc[i][j][q] = 0.0f;

    copy_chunk_256(A, lda, m0, B, ldb, 0, smem, smem + ASZ, tid);
    if (NC > 1)
        copy_chunk_256(A, lda, m0, B, ldb, 32, smem + BUFSZ, smem + BUFSZ + ASZ, tid);
    cp_wait<(NC > 1) ? 1 : 0>();
    __syncthreads();

    int bc = 0;
#pragma unroll 1
    for (int c = 0; c < NC; c++) {
        const float* As = smem + bc * BUFSZ;
        const float* Bs = As + ASZ;
        compute_chunk(As, Bs, acc, wm, wn, g, t);
        __syncthreads();
        if (c + 2 < NC) {
            int bl = bc + 2; if (bl >= 3) bl -= 3;
            float* Ad = smem + bl * BUFSZ;
            copy_chunk_256(A, lda, m0, B, ldb, (c + 2) * 32, Ad, Ad + ASZ, tid);
        }
        if (c + 1 < NC) {
            if (c + 2 < NC) cp_wait<1>(); else cp_wait<0>();
        }
        __syncthreads();
        if (++bc == 3) bc = 0;
    }
}

// ============================================================
// Kernel 1 (FUSED): merged QKV GEMM + rotary + attention + residual + LN1
// 256 threads / 8 warps, CTA = 64 rows = 2 locations. 2 CTAs/SM.
// Warp grid 2x4: warp tile 32 rows x 32 cols PER WEIGHT (3 acc sets).
// K chunk 16, double-buffered. smem peak = Q/K/V bufs = 101.4 KB.
// ============================================================
#define FP 132
#define M_AP 20                       // A pitch for 16-wide chunk (16+4)
#define M_ASZ (64*M_AP)               // 1280 floats
#define M_BSZ (16*BP)                 // 2176 floats per weight
#define M_BUF (M_ASZ + 3*M_BSZ)       // 7808 floats per stage
#define M_STAGE (2*M_BUF)             // 15616 floats
#define M_KBUF 0                      // overlays stage
#define M_VBUF (64*FP)                // 8448
#define M_QBUF (2*64*FP)              // 16896
#define M_SMEM_FLOATS (3*64*FP)       // 25344 floats
#define M_SMEM_BYTES (M_SMEM_FLOATS*4)  // 101376 B

__device__ __forceinline__ void m_copy_chunk(
    const float* __restrict__ x, int m0,
    const float* __restrict__ wk, const float* __restrict__ wv,
    const float* __restrict__ wq, int k0, float* buf, int tid)
{
    // A: 64 rows x 16 k (gathered from x: row r -> x[r&31][r>>5][:])
    const int ia = tid >> 2;            // 0..63
    const int kc = (tid & 3) * 4;       // 0,4,8,12
    const int r = m0 + ia;
    const size_t off = (size_t)(r & 31) * (NLOC * CDIM) + (size_t)(r >> 5) * CDIM;
    cp16(&buf[ia * M_AP + kc], &x[off + k0 + kc]);
    // B x3: each 16 k-rows x 128 cols
    const int kr = tid >> 4;            // 0..15
    const int nb = (tid & 15) * 8;      // 0..120
    const float* Ws[3] = { wk, wv, wq };
#pragma unroll
    for (int w = 0; w < 3; w++) {
        float* Bs = buf + M_ASZ + w * M_BSZ;
        cp16(&Bs[kr * BP + nb],     &Ws[w][(size_t)(k0 + kr) * CDIM + nb]);
        cp16(&Bs[kr * BP + nb + 4], &Ws[w][(size_t)(k0 + kr) * CDIM + nb + 4]);
    }
    cp_commit();
}

__device__ __forceinline__ void m_compute_chunk(
    const float* __restrict__ buf,
    float acc[3][2][4][4], int wm, int wn, int g, int t)
{
    const float* As = buf;
#pragma unroll
    for (int ks = 0; ks < 2; ks++) {
        const int kk = ks * 8;
        float a[2][4];
#pragma unroll
        for (int mf = 0; mf < 2; mf++) {
            const int row = wm * 32 + mf * 16 + g;
            a[mf][0] = As[row * M_AP + kk + t];
            a[mf][1] = As[(row + 8) * M_AP + kk + t];
            a[mf][2] = As[row * M_AP + kk + t + 4];
            a[mf][3] = As[(row + 8) * M_AP + kk + t + 4];
        }
#pragma unroll
        for (int w = 0; w < 3; w++) {
            const float* Bs = buf + M_ASZ + w * M_BSZ;
#pragma unroll
            for (int nf = 0; nf < 4; nf++) {
                const int n = wn * 32 + nf * 8 + g;
                float b[2];
                b[0] = Bs[(kk + t) * BP + n];
                b[1] = Bs[(kk + t + 4) * BP + n];
#pragma unroll
                for (int mf = 0; mf < 2; mf++)
                    mma8(acc[w][mf][nf], a[mf], b);
            }
        }
    }
}

__global__ __launch_bounds__(256, 2)
void k_fused_attn(const float* __restrict__ x,
                  const float* __restrict__ wq, const float* __restrict__ bq,
                  const float* __restrict__ wk, const float* __restrict__ bk,
                  const float* __restrict__ wv, const float* __restrict__ bv,
                  const float* __restrict__ ln1g, const float* __restrict__ ln1b)
{
    extern __shared__ float smem[];
    __shared__ float sinT[SEQ][8];
    __shared__ float cosT[SEQ][8];

    float* Kbuf = smem + M_KBUF;
    float* Vbuf = smem + M_VBUF;
    float* Qbuf = smem + M_QBUF;

    const int tid = threadIdx.x;
    const int warp = tid >> 5, lane = tid & 31;
    const int wm = warp >> 2, wn = warp & 3;       // 2x4 warp grid
    const int g = lane >> 2, t = lane & 3;
    const int m0 = blockIdx.x * 64;

    if (tid < SEQ * 8) {
        const int s = tid >> 3, j = tid & 7;
        const float ang = powf(10000.0f, -(float)j / 7.0f);
        float sv, cv;
        sincosf((float)s * ang, &sv, &cv);
        sinT[s][j] = sv;
        cosT[s][j] = cv;
    }

    // ---------- merged QKV mainloop (8 chunks of 16, double-buffered) ----------
    float acc[3][2][4][4];
#pragma unroll
    for (int w = 0; w < 3; w++)
#pragma unroll
        for (int i = 0; i < 2; i++)
#pragma unroll
            for (int j = 0; j < 4; j++)
#pragma unroll
                for (int q = 0; q < 4; q++) acc[w][i][j][q] = 0.0f;

    m_copy_chunk(x, m0, wk, wv, wq, 0,  smem,         tid);
    m_copy_chunk(x, m0, wk, wv, wq, 16, smem + M_BUF, tid);
    cp_wait<1>();
    __syncthreads();

#pragma unroll 1
    for (int c = 0; c < 8; c++) {
        const float* buf = smem + (c & 1) * M_BUF;
        m_compute_chunk(buf, acc, wm, wn, g, t);
        __syncthreads();
        if (c + 2 < 8)
            m_copy_chunk(x, m0, wk, wv, wq, (c + 2) * 16, smem + (c & 1) * M_BUF, tid);
        if (c + 1 < 8) {
            if (c + 2 < 8) cp_wait<1>(); else cp_wait<0>();
        }
        __syncthreads();
    }

    // ---------- epilogue: acc + bias -> K/V/Q smem tiles ----------
    {
        const float* biases[3] = { bk, bv, bq };
        float* dsts[3] = { Kbuf, Vbuf, Qbuf };
#pragma unroll
        for (int w = 0; w < 3; w++) {
            float* dst = dsts[w];
            const float* BIAS = biases[w];
#pragma unroll
            for (int nf = 0; nf < 4; nf++) {
                const int col = wn * 32 + nf * 8 + 2 * t;
                const float2 bv2 = *(const float2*)&BIAS[col];
#pragma unroll
                for (int mf = 0; mf < 2; mf++) {
                    const int row0 = wm * 32 + mf * 16 + g;
                    float2 o0, o1;
                    o0.x = acc[w][mf][nf][0] + bv2.x; o0.y = acc[w][mf][nf][1] + bv2.y;
                    o1.x = acc[w][mf][nf][2] + bv2.x; o1.y = acc[w][mf][nf][3] + bv2.y;
                    *(float2*)&dst[row0 * FP + col] = o0;
                    *(float2*)&dst[(row0 + 8) * FP + col] = o1;
                }
            }
        }
    }
    __syncthreads();

    // ---------- in-place rotary on Qbuf and Kbuf ----------
#pragma unroll
    for (int task = tid; task < 64 * NHEAD; task += 256) {
        const int row = task >> 3, h = task & 7;
        const int s = row & 31;
        float tq[HD], tk[HD];
#pragma unroll
        for (int d4 = 0; d4 < 4; d4++) {
            *(float4*)&tq[d4 * 4] = *(const float4*)&Qbuf[row * FP + h * 16 + d4 * 4];
            *(float4*)&tk[d4 * 4] = *(const float4*)&Kbuf[row * FP + h * 16 + d4 * 4];
        }
        float rq[HD], rk[HD];
#pragma unroll
        for (int d = 0; d < HD; d++) {
            const float sv = sinT[s][d >> 1];
            const float cv = cosT[s][d >> 1];
            const int pc = (d < 8) ? (2 * d + 1) : (2 * d - 16);
            const float sgn = (d < 8) ? -1.0f : 1.0f;
            rq[d] = tq[d] * cv + sgn * tq[pc] * sv;
            rk[d] = tk[d] * cv + sgn * tk[pc] * sv;
        }
#pragma unroll
        for (int d4 = 0; d4 < 4; d4++) {
            *(float4*)&Qbuf[row * FP + h * 16 + d4 * 4] = *(const float4*)&rq[d4 * 4];
            *(float4*)&Kbuf[row * FP + h * 16 + d4 * 4] = *(const float4*)&rk[d4 * 4];
        }
    }
    __syncthreads();

    // ---------- attention: warp w -> head w, locations 0 and 1 ----------
    const int h = warp;
    const float decay = log1pf(-exp2f(-(1.0f + 3.0f * (float)h / 8.0f)));

#pragma unroll
    for (int l = 0; l < 2; l++) {
        const int qrow = l * 32 + lane;

        u64t q2[8];
        {
            const float* qp = &Qbuf[qrow * FP + h * 16];
            ulonglong2 qa = *(const ulonglong2*)(qp);
            ulonglong2 qb = *(const ulonglong2*)(qp + 4);
            ulonglong2 qc = *(const ulonglong2*)(qp + 8);
            ulonglong2 qd = *(const ulonglong2*)(qp + 12);
            q2[0] = qa.x; q2[1] = qa.y; q2[2] = qb.x; q2[3] = qb.y;
            q2[4] = qc.x; q2[5] = qc.y; q2[6] = qd.x; q2[7] = qd.y;
        }

        float p[SEQ];
        float mx = -1e30f;
#pragma unroll
        for (int j = 0; j < SEQ; j++) {
            const float* kp = &Kbuf[(l * 32 + j) * FP + h * 16];
            ulonglong2 ka = *(const ulonglong2*)(kp);
            ulonglong2 kb = *(const ulonglong2*)(kp + 4);
            ulonglong2 kc = *(const ulonglong2*)(kp + 8);
            ulonglong2 kd = *(const ulonglong2*)(kp + 12);
            u64t s2 = 0ull;
            fma2(s2, q2[0], ka.x); fma2(s2, q2[1], ka.y);
            fma2(s2, q2[2], kb.x); fma2(s2, q2[3], kb.y);
            fma2(s2, q2[4], kc.x); fma2(s2, q2[5], kc.y);
            fma2(s2, q2[6], kd.x); fma2(s2, q2[7], kd.y);
            float lo, hi;
            upk2(s2, lo, hi);
            const float dot = lo + hi + fabsf((float)(lane - j)) * decay;
            p[j] = dot;
            mx = fmaxf(mx, dot);
        }
        float sum = 0.0f;
#pragma unroll
        for (int j = 0; j < SEQ; j++) { p[j] = expf(p[j] - mx); sum += p[j]; }
        const float inv = 1.0f / sum;

        u64t o2[8];
#pragma unroll
        for (int i = 0; i < 8; i++) o2[i] = 0ull;
#pragma unroll
        for (int j = 0; j < SEQ; j++) {
            const float* vp = &Vbuf[(l * 32 + j) * FP + h * 16];
            ulonglong2 va = *(const ulonglong2*)(vp);
            ulonglong2 vb = *(const ulonglong2*)(vp + 4);
            ulonglong2 vc = *(const ulonglong2*)(vp + 8);
            ulonglong2 vd = *(const ulonglong2*)(vp + 12);
            const u64t pj2 = pk2(p[j], p[j]);
            fma2(o2[0], va.x, pj2); fma2(o2[1], va.y, pj2);
            fma2(o2[2], vb.x, pj2); fma2(o2[3], vb.y, pj2);
            fma2(o2[4], vc.x, pj2); fma2(o2[5], vc.y, pj2);
            fma2(o2[6], vd.x, pj2); fma2(o2[7], vd.y, pj2);
        }
        float o[HD];
#pragma unroll
        for (int i = 0; i < 8; i++) {
            float lo, hi;
            upk2(o2[i], lo, hi);
            o[2 * i] = lo * inv;
            o[2 * i + 1] = hi * inv;
        }
#pragma unroll
        for (int d4 = 0; d4 < 4; d4++)
            *(float4*)&Qbuf[qrow * FP + h * 16 + d4 * 4] = *(const float4*)&o[d4 * 4];
    }
    __syncthreads();

    // ---------- residual + LN1 -> g_x1 ; 8 warps x 8 rows ----------
#pragma unroll
    for (int rr = 0; rr < 8; rr++) {
        const int row = warp * 8 + rr;
        const int r = m0 + row;
        const int c = lane * 4;
        float4 ov = *(const float4*)&Qbuf[row * FP + c];
        float4 xv = *(const float4*)&x[(size_t)(r & 31) * (NLOC * CDIM) + (size_t)(r >> 5) * CDIM + c];
        float v0 = ov.x + xv.x, v1 = ov.y + xv.y, v2 = ov.z + xv.z, v3 = ov.w + xv.w;
        float sum = v0 + v1 + v2 + v3;
        float sq  = v0 * v0 + v1 * v1 + v2 * v2 + v3 * v3;
#pragma unroll
        for (int off = 16; off > 0; off >>= 1) {
            sum += __shfl_xor_sync(0xffffffffu, sum, off);
            sq  += __shfl_xor_sync(0xffffffffu, sq,  off);
        }
        const float mu  = sum * (1.0f / 128.0f);
        const float var = sq * (1.0f / 128.0f) - mu * mu;
        const float wnr = rsqrtf(var + 1e-5f);
        float4 g4 = *(const float4*)&ln1g[c];
        float4 b4 = *(const float4*)&ln1b[c];
        float4 o;
        o.x = (v0 - mu) * wnr * g4.x + b4.x;
        o.y = (v1 - mu) * wnr * g4.y + b4.y;
        o.z = (v2 - mu) * wnr * g4.z + b4.z;
        o.w = (v3 - mu) * wnr * g4.w + b4.w;
        *(float4*)&g_x1[(size_t)r * CDIM + c] = o;
    }
}

// ============================================================
// Kernel 3: FFN1 H = relu(X1 @ W1 + b1)   (tf32 MMA, cp.async)
// ============================================================
__global__ __launch_bounds__(256, 2)
void k_ffn1(const float* __restrict__ w1, const float* __restrict__ b1)
{
    extern __shared__ float smem[];
    const int tid = threadIdx.x;
    const int warp = tid >> 5, lane = tid & 31;
    const int wm = warp >> 2, wn = warp & 3;
    const int g = lane >> 2, t = lane & 3;
    const int m0 = blockIdx.x * 128;
    const int bn0 = blockIdx.y * 128;

    float acc[4][4][4];
    run_gemm<4>(g_x1, CDIM, m0, w1 + bn0, FFND, acc, smem, tid, wm, wn, g, t);

#pragma unroll
    for (int nf = 0; nf < 4; nf++) {
        const int col = wn * 32 + nf * 8 + 2 * t;
        const float2 bv2 = *(const float2*)&b1[bn0 + col];
#pragma unroll
        for (int mf = 0; mf < 4; mf++) {
            const int r0 = m0 + wm * 64 + mf * 16 + g;
            float2 o0, o1;
            o0.x = fmaxf(acc[mf][nf][0] + bv2.x, 0.0f);
            o0.y = fmaxf(acc[mf][nf][1] + bv2.y, 0.0f);
            o1.x = fmaxf(acc[mf][nf][2] + bv2.x, 0.0f);
            o1.y = fmaxf(acc[mf][nf][3] + bv2.y, 0.0f);
            *(float2*)&g_h[(size_t)r0 * FFND + bn0 + col] = o0;
            *(float2*)&g_h[(size_t)(r0 + 8) * FFND + bn0 + col] = o1;
        }
    }
}

// ============================================================
// Kernel 4: FFN2 + residual + LN2 + transposed output
// ============================================================
#define TP 132
__global__ __launch_bounds__(256, 2)
void k_ffn2(const float* __restrict__ w2, const float* __restrict__ b2,
            const float* __restrict__ ln2g, const float* __restrict__ ln2b,
            float* __restrict__ out)
{
    extern __shared__ float smem[];
    const int tid = threadIdx.x;
    const int warp = tid >> 5, lane = tid & 31;
    const int wm = warp >> 2, wn = warp & 3;
    const int g = lane >> 2, t = lane & 3;
    const int m0 = blockIdx.x * 128;

    float acc[4][4][4];
    run_gemm<16>(g_h, FFND, m0, w2, CDIM, acc, smem, tid, wm, wn, g, t);

    float* T = smem;
#pragma unroll
    for (int nf = 0; nf < 4; nf++) {
        const int col = wn * 32 + nf * 8 + 2 * t;
        const float2 bv2 = *(const float2*)&b2[col];
#pragma unroll
        for (int mf = 0; mf < 4; mf++) {
            const int row0 = wm * 64 + mf * 16 + g;
            float2 o0, o1;
            o0.x = acc[mf][nf][0] + bv2.x; o0.y = acc[mf][nf][1] + bv2.y;
            o1.x = acc[mf][nf][2] + bv2.x; o1.y = acc[mf][nf][3] + bv2.y;
            *(float2*)&T[row0 * TP + col] = o0;
            *(float2*)&T[(row0 + 8) * TP + col] = o1;
        }
    }
    __syncthreads();

#pragma unroll
    for (int rr = 0; rr < 16; rr++) {
        const int row = warp * 16 + rr;
        const int r = m0 + row;
        const int c = lane * 4;
        float4 v = *(const float4*)&T[row * TP + c];
        float4 xv = *(const float4*)&g_x1[(size_t)r * CDIM + c];
        float v0 = v.x + xv.x, v1 = v.y + xv.y, v2 = v.z + xv.z, v3 = v.w + xv.w;
        float sum = v0 + v1 + v2 + v3;
        float sq  = v0 * v0 + v1 * v1 + v2 * v2 + v3 * v3;
#pragma unroll
        for (int off = 16; off > 0; off >>= 1) {
            sum += __shfl_xor_sync(0xffffffffu, sum, off);
            sq  += __shfl_xor_sync(0xffffffffu, sq,  off);
        }
        const float mu  = sum * (1.0f / 128.0f);
        const float var = sq * (1.0f / 128.0f) - mu * mu;
        const float wnr = rsqrtf(var + 1e-5f);
        float4 g4 = *(const float4*)&ln2g[c];
        float4 b4 = *(const float4*)&ln2b[c];
        float4 o;
        o.x = (v0 - mu) * wnr * g4.x + b4.x;
        o.y = (v1 - mu) * wnr * g4.y + b4.y;
        o.z = (v2 - mu) * wnr * g4.z + b4.z;
        o.w = (v3 - mu) * wnr * g4.w + b4.w;
        const int nn = r >> 5;
        const int ss = r & 31;
        *(float4*)&out[(size_t)ss * NLOC * CDIM + (size_t)nn * CDIM + c] = o;
    }
}

// ============================================================
extern "C" void kernel_launch(void* const* d_in, const int* in_sizes, int n_in,
                              void* d_out, int out_size)
{
    (void)in_sizes; (void)n_in; (void)out_size;
    const float* x    = (const float*)d_in[0];
    const float* wq   = (const float*)d_in[1];
    const float* bq   = (const float*)d_in[2];
    const float* wk   = (const float*)d_in[3];
    const float* bk   = (const float*)d_in[4];
    const float* wv   = (const float*)d_in[5];
    const float* bv   = (const float*)d_in[6];
    const float* ln1g = (const float*)d_in[7];
    const float* ln1b = (const float*)d_in[8];
    const float* w1   = (const float*)d_in[9];
    const float* b1   = (const float*)d_in[10];
    const float* w2   = (const float*)d_in[11];
    const float* b2   = (const float*)d_in[12];
    const float* ln2g = (const float*)d_in[13];
    const float* ln2b = (const float*)d_in[14];
    float* out = (float*)d_out;

    cudaFuncSetAttribute(k_fused_attn, cudaFuncAttributeMaxDynamicSharedMemorySize, M_SMEM_BYTES);
    cudaFuncSetAttribute(k_ffn1, cudaFuncAttributeMaxDynamicSharedMemorySize, G3_SMEM_BYTES);
    cudaFuncSetAttribute(k_ffn2, cudaFuncAttributeMaxDynamicSharedMemorySize, G3_SMEM_BYTES);

    k_fused_attn<<<MROWS / 64, 256, M_SMEM_BYTES>>>(x, wq, bq, wk, bk, wv, bv, ln1g, ln1b);

    dim3 g3(MROWS / 128, 4);
    k_ffn1<<<g3, 256, G3_SMEM_BYTES>>>(w1, b1);

    k_ffn2<<<MROWS / 128, 256, G3_SMEM_BYTES>>>(w2, b2, ln2g, ln2b, out);
}

// round 9
// speedup vs baseline: 1.2194x; 1.2194x over previous
#include <cuda_runtime.h>
#include <cuda_bf16.h>
#include <math.h>

#define NLOC 8192
#define SEQ 32
#define CDIM 128
#define NHEAD 8
#define HD 16
#define MROWS (NLOC*SEQ)   // 262144
#define FFND 512

// -------- scratch (static device globals; no runtime allocation) --------
__device__ float g_x1[(size_t)MROWS * CDIM];            // 128 MB (fp32 residual)
__device__ __nv_bfloat16 g_x1b[(size_t)MROWS * CDIM];   // 64 MB (ffn1 A operand)
__device__ __nv_bfloat16 g_hb[(size_t)MROWS * FFND];    // 256 MB (ffn2 A operand)
__device__ __nv_bfloat16 g_w1tb[(size_t)FFND * CDIM];   // w1^T bf16 [n=512][k=128]
__device__ __nv_bfloat16 g_w2tb[(size_t)CDIM * FFND];   // w2^T bf16 [n=128][k=512]

// ======================= mma / cp.async helpers =======================
__device__ __forceinline__ void mma8(float* c, const float* a, const float* b) {
    asm volatile(
        "mma.sync.aligned.m16n8k8.row.col.f32.tf32.tf32.f32 "
        "{%0,%1,%2,%3}, {%4,%5,%6,%7}, {%8,%9}, {%0,%1,%2,%3};"
        : "+f"(c[0]), "+f"(c[1]), "+f"(c[2]), "+f"(c[3])
        : "r"(__float_as_uint(a[0])), "r"(__float_as_uint(a[1])),
          "r"(__float_as_uint(a[2])), "r"(__float_as_uint(a[3])),
          "r"(__float_as_uint(b[0])), "r"(__float_as_uint(b[1])));
}

// bf16 mma: m16n8k16, fp32 accumulate
__device__ __forceinline__ void mma16(float* c, const unsigned* a, const unsigned* b) {
    asm volatile(
        "mma.sync.aligned.m16n8k16.row.col.f32.bf16.bf16.f32 "
        "{%0,%1,%2,%3}, {%4,%5,%6,%7}, {%8,%9}, {%0,%1,%2,%3};"
        : "+f"(c[0]), "+f"(c[1]), "+f"(c[2]), "+f"(c[3])
        : "r"(a[0]), "r"(a[1]), "r"(a[2]), "r"(a[3]),
          "r"(b[0]), "r"(b[1]));
}

__device__ __forceinline__ void cp16(void* s, const void* g) {
    unsigned saddr = (unsigned)__cvta_generic_to_shared(s);
    asm volatile("cp.async.cg.shared.global [%0], [%1], 16;" :: "r"(saddr), "l"(g));
}
__device__ __forceinline__ void cp_commit() {
    asm volatile("cp.async.commit_group;");
}
template<int N>
__device__ __forceinline__ void cp_wait() {
    asm volatile("cp.async.wait_group %0;" :: "n"(N));
}

// packed f32x2
typedef unsigned long long u64t;
__device__ __forceinline__ u64t pk2(float lo, float hi) {
    u64t r; asm("mov.b64 %0,{%1,%2};" : "=l"(r) : "f"(lo), "f"(hi)); return r;
}
__device__ __forceinline__ void upk2(u64t v, float& lo, float& hi) {
    asm("mov.b64 {%0,%1},%2;" : "=f"(lo), "=f"(hi) : "l"(v));
}
__device__ __forceinline__ void fma2(u64t& d, u64t a, u64t b) {
    asm("fma.rn.f32x2 %0,%1,%2,%0;" : "+l"(d) : "l"(a), "l"(b));
}

// ============================================================
// Kernel 0: transpose + convert weights to bf16 (n-major)
// ============================================================
__global__ void k_wtb(const float* __restrict__ w1, const float* __restrict__ w2)
{
    __shared__ float t[32][33];
    const int which = blockIdx.z;
    const float* src = which ? w2 : w1;
    const int R = which ? 512 : 128;   // src rows (k)
    const int C = which ? 128 : 512;   // src cols (n)
    const int r0 = blockIdx.y * 32, c0 = blockIdx.x * 32;
    if (r0 >= R || c0 >= C) return;
    const int lx = threadIdx.x, ly = threadIdx.y;
#pragma unroll
    for (int i = 0; i < 32; i += 8)
        t[ly + i][lx] = src[(size_t)(r0 + ly + i) * C + c0 + lx];
    __syncthreads();
    __nv_bfloat16* dst = which ? g_w2tb : g_w1tb;
#pragma unroll
    for (int i = 0; i < 32; i += 8)
        dst[(size_t)(c0 + ly + i) * R + r0 + lx] = __float2bfloat16(t[lx][ly + i]);
}

// ============================================================
// Kernel 1 (FUSED): merged QKV GEMM + rotary + attention + residual + LN1
// (Round-7 structure; epilogue additionally writes bf16 x1 copy)
// ============================================================
#define BP 136
#define FP 132
#define M_AP 20
#define M_ASZ (64*M_AP)
#define M_BSZ (16*BP)
#define M_BUF (M_ASZ + 3*M_BSZ)
#define M_STAGE (2*M_BUF)
#define M_KBUF 0
#define M_VBUF (64*FP)
#define M_QBUF (2*64*FP)
#define M_SMEM_FLOATS (3*64*FP)
#define M_SMEM_BYTES (M_SMEM_FLOATS*4)

__device__ __forceinline__ void m_copy_chunk(
    const float* __restrict__ x, int m0,
    const float* __restrict__ wk, const float* __restrict__ wv,
    const float* __restrict__ wq, int k0, float* buf, int tid)
{
    const int ia = tid >> 2;
    const int kc = (tid & 3) * 4;
    const int r = m0 + ia;
    const size_t off = (size_t)(r & 31) * (NLOC * CDIM) + (size_t)(r >> 5) * CDIM;
    cp16(&buf[ia * M_AP + kc], &x[off + k0 + kc]);
    const int kr = tid >> 4;
    const int nb = (tid & 15) * 8;
    const float* Ws[3] = { wk, wv, wq };
#pragma unroll
    for (int w = 0; w < 3; w++) {
        float* Bs = buf + M_ASZ + w * M_BSZ;
        cp16(&Bs[kr * BP + nb],     &Ws[w][(size_t)(k0 + kr) * CDIM + nb]);
        cp16(&Bs[kr * BP + nb + 4], &Ws[w][(size_t)(k0 + kr) * CDIM + nb + 4]);
    }
    cp_commit();
}

__device__ __forceinline__ void m_compute_chunk(
    const float* __restrict__ buf,
    float acc[3][2][4][4], int wm, int wn, int g, int t)
{
    const float* As = buf;
#pragma unroll
    for (int ks = 0; ks < 2; ks++) {
        const int kk = ks * 8;
        float a[2][4];
#pragma unroll
        for (int mf = 0; mf < 2; mf++) {
            const int row = wm * 32 + mf * 16 + g;
            a[mf][0] = As[row * M_AP + kk + t];
            a[mf][1] = As[(row + 8) * M_AP + kk + t];
            a[mf][2] = As[row * M_AP + kk + t + 4];
            a[mf][3] = As[(row + 8) * M_AP + kk + t + 4];
        }
#pragma unroll
        for (int w = 0; w < 3; w++) {
            const float* Bs = buf + M_ASZ + w * M_BSZ;
#pragma unroll
            for (int nf = 0; nf < 4; nf++) {
                const int n = wn * 32 + nf * 8 + g;
                float b[2];
                b[0] = Bs[(kk + t) * BP + n];
                b[1] = Bs[(kk + t + 4) * BP + n];
#pragma unroll
                for (int mf = 0; mf < 2; mf++)
                    mma8(acc[w][mf][nf], a[mf], b);
            }
        }
    }
}

__global__ __launch_bounds__(256, 2)
void k_fused_attn(const float* __restrict__ x,
                  const float* __restrict__ wq, const float* __restrict__ bq,
                  const float* __restrict__ wk, const float* __restrict__ bk,
                  const float* __restrict__ wv, const float* __restrict__ bv,
                  const float* __restrict__ ln1g, const float* __restrict__ ln1b)
{
    extern __shared__ float smem[];
    __shared__ float sinT[SEQ][8];
    __shared__ float cosT[SEQ][8];

    float* Kbuf = smem + M_KBUF;
    float* Vbuf = smem + M_VBUF;
    float* Qbuf = smem + M_QBUF;

    const int tid = threadIdx.x;
    const int warp = tid >> 5, lane = tid & 31;
    const int wm = warp >> 2, wn = warp & 3;
    const int g = lane >> 2, t = lane & 3;
    const int m0 = blockIdx.x * 64;

    if (tid < SEQ * 8) {
        const int s = tid >> 3, j = tid & 7;
        const float ang = powf(10000.0f, -(float)j / 7.0f);
        float sv, cv;
        sincosf((float)s * ang, &sv, &cv);
        sinT[s][j] = sv;
        cosT[s][j] = cv;
    }

    float acc[3][2][4][4];
#pragma unroll
    for (int w = 0; w < 3; w++)
#pragma unroll
        for (int i = 0; i < 2; i++)
#pragma unroll
            for (int j = 0; j < 4; j++)
#pragma unroll
                for (int q = 0; q < 4; q++) acc[w][i][j][q] = 0.0f;

    m_copy_chunk(x, m0, wk, wv, wq, 0,  smem,         tid);
    m_copy_chunk(x, m0, wk, wv, wq, 16, smem + M_BUF, tid);
    cp_wait<1>();
    __syncthreads();

#pragma unroll 1
    for (int c = 0; c < 8; c++) {
        const float* buf = smem + (c & 1) * M_BUF;
        m_compute_chunk(buf, acc, wm, wn, g, t);
        __syncthreads();
        if (c + 2 < 8)
            m_copy_chunk(x, m0, wk, wv, wq, (c + 2) * 16, smem + (c & 1) * M_BUF, tid);
        if (c + 1 < 8) {
            if (c + 2 < 8) cp_wait<1>(); else cp_wait<0>();
        }
        __syncthreads();
    }

    {
        const float* biases[3] = { bk, bv, bq };
        float* dsts[3] = { Kbuf, Vbuf, Qbuf };
#pragma unroll
        for (int w = 0; w < 3; w++) {
            float* dst = dsts[w];
            const float* BIAS = biases[w];
#pragma unroll
            for (int nf = 0; nf < 4; nf++) {
                const int col = wn * 32 + nf * 8 + 2 * t;
                const float2 bv2 = *(const float2*)&BIAS[col];
#pragma unroll
                for (int mf = 0; mf < 2; mf++) {
                    const int row0 = wm * 32 + mf * 16 + g;
                    float2 o0, o1;
                    o0.x = acc[w][mf][nf][0] + bv2.x; o0.y = acc[w][mf][nf][1] + bv2.y;
                    o1.x = acc[w][mf][nf][2] + bv2.x; o1.y = acc[w][mf][nf][3] + bv2.y;
                    *(float2*)&dst[row0 * FP + col] = o0;
                    *(float2*)&dst[(row0 + 8) * FP + col] = o1;
                }
            }
        }
    }
    __syncthreads();

#pragma unroll
    for (int task = tid; task < 64 * NHEAD; task += 256) {
        const int row = task >> 3, h = task & 7;
        const int s = row & 31;
        float tq[HD], tk[HD];
#pragma unroll
        for (int d4 = 0; d4 < 4; d4++) {
            *(float4*)&tq[d4 * 4] = *(const float4*)&Qbuf[row * FP + h * 16 + d4 * 4];
            *(float4*)&tk[d4 * 4] = *(const float4*)&Kbuf[row * FP + h * 16 + d4 * 4];
        }
        float rq[HD], rk[HD];
#pragma unroll
        for (int d = 0; d < HD; d++) {
            const float sv = sinT[s][d >> 1];
            const float cv = cosT[s][d >> 1];
            const int pc = (d < 8) ? (2 * d + 1) : (2 * d - 16);
            const float sgn = (d < 8) ? -1.0f : 1.0f;
            rq[d] = tq[d] * cv + sgn * tq[pc] * sv;
            rk[d] = tk[d] * cv + sgn * tk[pc] * sv;
        }
#pragma unroll
        for (int d4 = 0; d4 < 4; d4++) {
            *(float4*)&Qbuf[row * FP + h * 16 + d4 * 4] = *(const float4*)&rq[d4 * 4];
            *(float4*)&Kbuf[row * FP + h * 16 + d4 * 4] = *(const float4*)&rk[d4 * 4];
        }
    }
    __syncthreads();

    const int h = warp;
    const float decay = log1pf(-exp2f(-(1.0f + 3.0f * (float)h / 8.0f)));

#pragma unroll
    for (int l = 0; l < 2; l++) {
        const int qrow = l * 32 + lane;

        u64t q2[8];
        {
            const float* qp = &Qbuf[qrow * FP + h * 16];
            ulonglong2 qa = *(const ulonglong2*)(qp);
            ulonglong2 qb = *(const ulonglong2*)(qp + 4);
            ulonglong2 qc = *(const ulonglong2*)(qp + 8);
            ulonglong2 qd = *(const ulonglong2*)(qp + 12);
            q2[0] = qa.x; q2[1] = qa.y; q2[2] = qb.x; q2[3] = qb.y;
            q2[4] = qc.x; q2[5] = qc.y; q2[6] = qd.x; q2[7] = qd.y;
        }

        float p[SEQ];
        float mx = -1e30f;
#pragma unroll
        for (int j = 0; j < SEQ; j++) {
            const float* kp = &Kbuf[(l * 32 + j) * FP + h * 16];
            ulonglong2 ka = *(const ulonglong2*)(kp);
            ulonglong2 kb = *(const ulonglong2*)(kp + 4);
            ulonglong2 kc = *(const ulonglong2*)(kp + 8);
            ulonglong2 kd = *(const ulonglong2*)(kp + 12);
            u64t s2 = 0ull;
            fma2(s2, q2[0], ka.x); fma2(s2, q2[1], ka.y);
            fma2(s2, q2[2], kb.x); fma2(s2, q2[3], kb.y);
            fma2(s2, q2[4], kc.x); fma2(s2, q2[5], kc.y);
            fma2(s2, q2[6], kd.x); fma2(s2, q2[7], kd.y);
            float lo, hi;
            upk2(s2, lo, hi);
            const float dot = lo + hi + fabsf((float)(lane - j)) * decay;
            p[j] = dot;
            mx = fmaxf(mx, dot);
        }
        float sum = 0.0f;
#pragma unroll
        for (int j = 0; j < SEQ; j++) { p[j] = expf(p[j] - mx); sum += p[j]; }
        const float inv = 1.0f / sum;

        u64t o2[8];
#pragma unroll
        for (int i = 0; i < 8; i++) o2[i] = 0ull;
#pragma unroll
        for (int j = 0; j < SEQ; j++) {
            const float* vp = &Vbuf[(l * 32 + j) * FP + h * 16];
            ulonglong2 va = *(const ulonglong2*)(vp);
            ulonglong2 vb = *(const ulonglong2*)(vp + 4);
            ulonglong2 vc = *(const ulonglong2*)(vp + 8);
            ulonglong2 vd = *(const ulonglong2*)(vp + 12);
            const u64t pj2 = pk2(p[j], p[j]);
            fma2(o2[0], va.x, pj2); fma2(o2[1], va.y, pj2);
            fma2(o2[2], vb.x, pj2); fma2(o2[3], vb.y, pj2);
            fma2(o2[4], vc.x, pj2); fma2(o2[5], vc.y, pj2);
            fma2(o2[6], vd.x, pj2); fma2(o2[7], vd.y, pj2);
        }
        float o[HD];
#pragma unroll
        for (int i = 0; i < 8; i++) {
            float lo, hi;
            upk2(o2[i], lo, hi);
            o[2 * i] = lo * inv;
            o[2 * i + 1] = hi * inv;
        }
#pragma unroll
        for (int d4 = 0; d4 < 4; d4++)
            *(float4*)&Qbuf[qrow * FP + h * 16 + d4 * 4] = *(const float4*)&o[d4 * 4];
    }
    __syncthreads();

    // residual + LN1 -> g_x1 (fp32) and g_x1b (bf16)
#pragma unroll
    for (int rr = 0; rr < 8; rr++) {
        const int row = warp * 8 + rr;
        const int r = m0 + row;
        const int c = lane * 4;
        float4 ov = *(const float4*)&Qbuf[row * FP + c];
        float4 xv = *(const float4*)&x[(size_t)(r & 31) * (NLOC * CDIM) + (size_t)(r >> 5) * CDIM + c];
        float v0 = ov.x + xv.x, v1 = ov.y + xv.y, v2 = ov.z + xv.z, v3 = ov.w + xv.w;
        float sum = v0 + v1 + v2 + v3;
        float sq  = v0 * v0 + v1 * v1 + v2 * v2 + v3 * v3;
#pragma unroll
        for (int off = 16; off > 0; off >>= 1) {
            sum += __shfl_xor_sync(0xffffffffu, sum, off);
            sq  += __shfl_xor_sync(0xffffffffu, sq,  off);
        }
        const float mu  = sum * (1.0f / 128.0f);
        const float var = sq * (1.0f / 128.0f) - mu * mu;
        const float wnr = rsqrtf(var + 1e-5f);
        float4 g4 = *(const float4*)&ln1g[c];
        float4 b4 = *(const float4*)&ln1b[c];
        float4 o;
        o.x = (v0 - mu) * wnr * g4.x + b4.x;
        o.y = (v1 - mu) * wnr * g4.y + b4.y;
        o.z = (v2 - mu) * wnr * g4.z + b4.z;
        o.w = (v3 - mu) * wnr * g4.w + b4.w;
        *(float4*)&g_x1[(size_t)r * CDIM + c] = o;
        __nv_bfloat162* bd = (__nv_bfloat162*)&g_x1b[(size_t)r * CDIM + c];
        bd[0] = __floats2bfloat162_rn(o.x, o.y);
        bd[1] = __floats2bfloat162_rn(o.z, o.w);
    }
}

// ============================================================
// Kernel 2: FFN1 bf16  H = relu(x1b @ w1 + b1)
// 256 thr, 8 warps (2x4), CTA = 128 rows, A resident, loops 4 N-tiles.
// smem (32b words): A[128][68]=8704 | B0 8704 | B1 8704 -> 104448 B
// ============================================================
#define F1W 68
#define F1_B0 8704
#define F1_B1 17408
#define F1_SMEM_BYTES (26112*4)

__device__ __forceinline__ void f1_stage_b(unsigned* sm_u, int dstoff, int nt, int tid)
{
#pragma unroll
    for (int j = 0; j < 8; j++) {
        const int i = tid + j * 256;
        const int row = i >> 4, u = i & 15;
        cp16(&sm_u[dstoff + row * F1W + u * 4],
             &g_w1tb[(size_t)(nt * 128 + row) * CDIM + u * 8]);
    }
    cp_commit();
}

__global__ __launch_bounds__(256, 2)
void k_ffn1_bf(const float* __restrict__ b1)
{
    extern __shared__ unsigned sm_u[];
    const int tid = threadIdx.x;
    const int warp = tid >> 5, lane = tid & 31;
    const int wm = warp >> 2, wn = warp & 3;
    const int g = lane >> 2, t = lane & 3;
    const int m0 = blockIdx.x * 128;

    // stage A (128x128 bf16) + B tile 0 (group 0), B tile 1 (group 1)
#pragma unroll
    for (int j = 0; j < 8; j++) {
        const int i = tid + j * 256;
        const int row = i >> 4, u = i & 15;
        cp16(&sm_u[row * F1W + u * 4],
             &g_x1b[(size_t)(m0 + row) * CDIM + u * 8]);
    }
#pragma unroll
    for (int j = 0; j < 8; j++) {
        const int i = tid + j * 256;
        const int row = i >> 4, u = i & 15;
        cp16(&sm_u[F1_B0 + row * F1W + u * 4],
             &g_w1tb[(size_t)row * CDIM + u * 8]);
    }
    cp_commit();
    f1_stage_b(sm_u, F1_B1, 1, tid);
    cp_wait<1>();
    __syncthreads();

#pragma unroll 1
    for (int nt = 0; nt < 4; nt++) {
        const unsigned* Bs = &sm_u[(nt & 1) ? F1_B1 : F1_B0];
        float acc[4][4][4];
#pragma unroll
        for (int i = 0; i < 4; i++)
#pragma unroll
            for (int j = 0; j < 4; j++)
#pragma unroll
                for (int q = 0; q < 4; q++) acc[i][j][q] = 0.0f;

#pragma unroll
        for (int s = 0; s < 8; s++) {
            unsigned aw[4][4];
#pragma unroll
            for (int mf = 0; mf < 4; mf++) {
                const int row = wm * 64 + mf * 16 + g;
                aw[mf][0] = sm_u[row * F1W + s * 8 + t];
                aw[mf][1] = sm_u[(row + 8) * F1W + s * 8 + t];
                aw[mf][2] = sm_u[row * F1W + s * 8 + t + 4];
                aw[mf][3] = sm_u[(row + 8) * F1W + s * 8 + t + 4];
            }
#pragma unroll
            for (int nf = 0; nf < 4; nf++) {
                const int n = wn * 32 + nf * 8 + g;
                unsigned bw[2];
                bw[0] = Bs[n * F1W + s * 8 + t];
                bw[1] = Bs[n * F1W + s * 8 + t + 4];
#pragma unroll
                for (int mf = 0; mf < 4; mf++)
                    mma16(acc[mf][nf], aw[mf], bw);
            }
        }

        // epilogue: bias + relu -> g_hb (bf16)
#pragma unroll
        for (int nf = 0; nf < 4; nf++) {
            const int col = wn * 32 + nf * 8 + 2 * t;
            const float2 bb = *(const float2*)&b1[nt * 128 + col];
#pragma unroll
            for (int mf = 0; mf < 4; mf++) {
                const int r0 = m0 + wm * 64 + mf * 16 + g;
                float h00 = fmaxf(acc[mf][nf][0] + bb.x, 0.0f);
                float h01 = fmaxf(acc[mf][nf][1] + bb.y, 0.0f);
                float h10 = fmaxf(acc[mf][nf][2] + bb.x, 0.0f);
                float h11 = fmaxf(acc[mf][nf][3] + bb.y, 0.0f);
                *(__nv_bfloat162*)&g_hb[(size_t)r0 * FFND + nt * 128 + col] =
                    __floats2bfloat162_rn(h00, h01);
                *(__nv_bfloat162*)&g_hb[(size_t)(r0 + 8) * FFND + nt * 128 + col] =
                    __floats2bfloat162_rn(h10, h11);
            }
        }
        __syncthreads();
        if (nt + 2 < 4) {
            f1_stage_b(sm_u, (nt & 1) ? F1_B1 : F1_B0, nt + 2, tid);
            cp_wait<1>();
            __syncthreads();
        } else if (nt + 1 < 4) {
            cp_wait<0>();
            __syncthreads();
        }
    }
}

// ============================================================
// Kernel 3: FFN2 bf16 + residual + LN2 + transposed output
// 256 thr, K=512 in 8 chunks of 64, double-buffered.
// smem (32b words): A0[128][36]=4608 | A1 | B0 | B1 -> 73728 B
// T epilogue (128x132 fp32 = 16896 words) overlays A0/A1.
// ============================================================
#define F2W 36
#define F2_A1 4608
#define F2_B0 9216
#define F2_B1 13824
#define F2_SMEM_BYTES (18432*4)
#define TP 132

__device__ __forceinline__ void f2_stage(unsigned* sm_u, int m0, int c, int buf, int tid)
{
    const int aoff = buf ? F2_A1 : 0;
    const int boff = buf ? F2_B1 : F2_B0;
#pragma unroll
    for (int j = 0; j < 4; j++) {
        const int i = tid + j * 256;
        const int row = i >> 3, u = i & 7;
        cp16(&sm_u[aoff + row * F2W + u * 4],
             &g_hb[(size_t)(m0 + row) * FFND + c * 64 + u * 8]);
        cp16(&sm_u[boff + row * F2W + u * 4],
             &g_w2tb[(size_t)row * FFND + c * 64 + u * 8]);
    }
    cp_commit();
}

__global__ __launch_bounds__(256, 2)
void k_ffn2_bf(const float* __restrict__ b2,
               const float* __restrict__ ln2g, const float* __restrict__ ln2b,
               float* __restrict__ out)
{
    extern __shared__ unsigned sm_u[];
    const int tid = threadIdx.x;
    const int warp = tid >> 5, lane = tid & 31;
    const int wm = warp >> 2, wn = warp & 3;
    const int g = lane >> 2, t = lane & 3;
    const int m0 = blockIdx.x * 128;

    float acc[4][4][4];
#pragma unroll
    for (int i = 0; i < 4; i++)
#pragma unroll
        for (int j = 0; j < 4; j++)
#pragma unroll
            for (int q = 0; q < 4; q++) acc[i][j][q] = 0.0f;

    f2_stage(sm_u, m0, 0, 0, tid);
    f2_stage(sm_u, m0, 1, 1, tid);
    cp_wait<1>();
    __syncthreads();

#pragma unroll 1
    for (int c = 0; c < 8; c++) {
        const unsigned* As = &sm_u[(c & 1) ? F2_A1 : 0];
        const unsigned* Bs = &sm_u[(c & 1) ? F2_B1 : F2_B0];
#pragma unroll
        for (int s = 0; s < 4; s++) {
            unsigned aw[4][4];
#pragma unroll
            for (int mf = 0; mf < 4; mf++) {
                const int row = wm * 64 + mf * 16 + g;
                aw[mf][0] = As[row * F2W + s * 8 + t];
                aw[mf][1] = As[(row + 8) * F2W + s * 8 + t];
                aw[mf][2] = As[row * F2W + s * 8 + t + 4];
                aw[mf][3] = As[(row + 8) * F2W + s * 8 + t + 4];
            }
#pragma unroll
            for (int nf = 0; nf < 4; nf++) {
                const int n = wn * 32 + nf * 8 + g;
                unsigned bw[2];
                bw[0] = Bs[n * F2W + s * 8 + t];
                bw[1] = Bs[n * F2W + s * 8 + t + 4];
#pragma unroll
                for (int mf = 0; mf < 4; mf++)
                    mma16(acc[mf][nf], aw[mf], bw);
            }
        }
        __syncthreads();
        if (c + 2 < 8) {
            f2_stage(sm_u, m0, c + 2, c & 1, tid);
            cp_wait<1>();
            __syncthreads();
        } else if (c + 1 < 8) {
            cp_wait<0>();
            __syncthreads();
        }
    }
    __syncthreads();

    // epilogue: stage (acc + bias) to T, then residual + LN2 + transposed store
    float* T = (float*)sm_u;
#pragma unroll
    for (int nf = 0; nf < 4; nf++) {
        const int col = wn * 32 + nf * 8 + 2 * t;
        const float2 bb = *(const float2*)&b2[col];
#pragma unroll
        for (int mf = 0; mf < 4; mf++) {
            const int row0 = wm * 64 + mf * 16 + g;
            float2 o0, o1;
            o0.x = acc[mf][nf][0] + bb.x; o0.y = acc[mf][nf][1] + bb.y;
            o1.x = acc[mf][nf][2] + bb.x; o1.y = acc[mf][nf][3] + bb.y;
            *(float2*)&T[row0 * TP + col] = o0;
            *(float2*)&T[(row0 + 8) * TP + col] = o1;
        }
    }
    __syncthreads();

#pragma unroll
    for (int rr = 0; rr < 16; rr++) {
        const int row = warp * 16 + rr;
        const int r = m0 + row;
        const int c = lane * 4;
        float4 v = *(const float4*)&T[row * TP + c];
        float4 xv = *(const float4*)&g_x1[(size_t)r * CDIM + c];
        float v0 = v.x + xv.x, v1 = v.y + xv.y, v2 = v.z + xv.z, v3 = v.w + xv.w;
        float sum = v0 + v1 + v2 + v3;
        float sq  = v0 * v0 + v1 * v1 + v2 * v2 + v3 * v3;
#pragma unroll
        for (int off = 16; off > 0; off >>= 1) {
            sum += __shfl_xor_sync(0xffffffffu, sum, off);
            sq  += __shfl_xor_sync(0xffffffffu, sq,  off);
        }
        const float mu  = sum * (1.0f / 128.0f);
        const float var = sq * (1.0f / 128.0f) - mu * mu;
        const float wnr = rsqrtf(var + 1e-5f);
        float4 g4 = *(const float4*)&ln2g[c];
        float4 b4 = *(const float4*)&ln2b[c];
        float4 o;
        o.x = (v0 - mu) * wnr * g4.x + b4.x;
        o.y = (v1 - mu) * wnr * g4.y + b4.y;
        o.z = (v2 - mu) * wnr * g4.z + b4.z;
        o.w = (v3 - mu) * wnr * g4.w + b4.w;
        const int nn = r >> 5;
        const int ss = r & 31;
        *(float4*)&out[(size_t)ss * NLOC * CDIM + (size_t)nn * CDIM + c] = o;
    }
}

// ============================================================
extern "C" void kernel_launch(void* const* d_in, const int* in_sizes, int n_in,
                              void* d_out, int out_size)
{
    (void)in_sizes; (void)n_in; (void)out_size;
    const float* x    = (const float*)d_in[0];
    const float* wq   = (const float*)d_in[1];
    const float* bq   = (const float*)d_in[2];
    const float* wk   = (const float*)d_in[3];
    const float* bk   = (const float*)d_in[4];
    const float* wv   = (const float*)d_in[5];
    const float* bv   = (const float*)d_in[6];
    const float* ln1g = (const float*)d_in[7];
    const float* ln1b = (const float*)d_in[8];
    const float* w1   = (const float*)d_in[9];
    const float* b1   = (const float*)d_in[10];
    const float* w2   = (const float*)d_in[11];
    const float* b2   = (const float*)d_in[12];
    const float* ln2g = (const float*)d_in[13];
    const float* ln2b = (const float*)d_in[14];
    float* out = (float*)d_out;

    cudaFuncSetAttribute(k_fused_attn, cudaFuncAttributeMaxDynamicSharedMemorySize, M_SMEM_BYTES);
    cudaFuncSetAttribute(k_ffn1_bf, cudaFuncAttributeMaxDynamicSharedMemorySize, F1_SMEM_BYTES);
    cudaFuncSetAttribute(k_ffn2_bf, cudaFuncAttributeMaxDynamicSharedMemorySize, F2_SMEM_BYTES);

    dim3 tg(16, 16, 2), tb(32, 8);
    k_wtb<<<tg, tb>>>(w1, w2);

    k_fused_attn<<<MROWS / 64, 256, M_SMEM_BYTES>>>(x, wq, bq, wk, bk, wv, bv, ln1g, ln1b);

    k_ffn1_bf<<<MROWS / 128, 256, F1_SMEM_BYTES>>>(b1);

    k_ffn2_bf<<<MROWS / 128, 256, F2_SMEM_BYTES>>>(b2, ln2g, ln2b, out);
}

// round 10
// speedup vs baseline: 1.2487x; 1.0240x over previous
#include <cuda_runtime.h>
#include <cuda_bf16.h>
#include <math.h>

#define NLOC 8192
#define SEQ 32
#define CDIM 128
#define NHEAD 8
#define HD 16
#define MROWS (NLOC*SEQ)   // 262144
#define FFND 512

// -------- scratch (static device globals; no runtime allocation) --------
__device__ float g_x1[(size_t)MROWS * CDIM];            // fp32 residual
__device__ __nv_bfloat16 g_x1b[(size_t)MROWS * CDIM];   // ffn1 A operand
__device__ __nv_bfloat16 g_hb[(size_t)MROWS * FFND];    // ffn2 A operand
__device__ __nv_bfloat16 g_w1tb[(size_t)FFND * CDIM];   // w1^T bf16 [512][128]
__device__ __nv_bfloat16 g_w2tb[(size_t)CDIM * FFND];   // w2^T bf16 [128][512]
__device__ __nv_bfloat16 g_wqtb[(size_t)CDIM * CDIM];   // wq^T bf16 [n][k]
__device__ __nv_bfloat16 g_wktb[(size_t)CDIM * CDIM];
__device__ __nv_bfloat16 g_wvtb[(size_t)CDIM * CDIM];

// ======================= mma / cp.async helpers =======================
// bf16 mma: m16n8k16, fp32 accumulate
__device__ __forceinline__ void mma16(float* c, const unsigned* a, const unsigned* b) {
    asm volatile(
        "mma.sync.aligned.m16n8k16.row.col.f32.bf16.bf16.f32 "
        "{%0,%1,%2,%3}, {%4,%5,%6,%7}, {%8,%9}, {%0,%1,%2,%3};"
        : "+f"(c[0]), "+f"(c[1]), "+f"(c[2]), "+f"(c[3])
        : "r"(a[0]), "r"(a[1]), "r"(a[2]), "r"(a[3]),
          "r"(b[0]), "r"(b[1]));
}

__device__ __forceinline__ void cp16(void* s, const void* g) {
    unsigned saddr = (unsigned)__cvta_generic_to_shared(s);
    asm volatile("cp.async.cg.shared.global [%0], [%1], 16;" :: "r"(saddr), "l"(g));
}
__device__ __forceinline__ void cp_commit() {
    asm volatile("cp.async.commit_group;");
}
template<int N>
__device__ __forceinline__ void cp_wait() {
    asm volatile("cp.async.wait_group %0;" :: "n"(N));
}

// packed f32x2
typedef unsigned long long u64t;
__device__ __forceinline__ u64t pk2(float lo, float hi) {
    u64t r; asm("mov.b64 %0,{%1,%2};" : "=l"(r) : "f"(lo), "f"(hi)); return r;
}
__device__ __forceinline__ void upk2(u64t v, float& lo, float& hi) {
    asm("mov.b64 {%0,%1},%2;" : "=f"(lo), "=f"(hi) : "l"(v));
}
__device__ __forceinline__ void fma2(u64t& d, u64t a, u64t b) {
    asm("fma.rn.f32x2 %0,%1,%2,%0;" : "+l"(d) : "l"(a), "l"(b));
}

// ============================================================
// Kernel 0: transpose + convert all weights to bf16 (n-major)
// which: 0=w1 1=w2 2=wq 3=wk 4=wv
// ============================================================
__global__ void k_wtb(const float* __restrict__ w1, const float* __restrict__ w2,
                      const float* __restrict__ wq, const float* __restrict__ wk,
                      const float* __restrict__ wv)
{
    __shared__ float t[32][33];
    const int which = blockIdx.z;
    const float* srcs[5] = { w1, w2, wq, wk, wv };
    __nv_bfloat16* dsts[5] = { g_w1tb, g_w2tb, g_wqtb, g_wktb, g_wvtb };
    const int Rs[5] = { 128, 512, 128, 128, 128 };   // src rows (k)
    const int Cs[5] = { 512, 128, 128, 128, 128 };   // src cols (n)
    const float* src = srcs[which];
    __nv_bfloat16* dst = dsts[which];
    const int R = Rs[which], C = Cs[which];
    const int r0 = blockIdx.y * 32, c0 = blockIdx.x * 32;
    if (r0 >= R || c0 >= C) return;
    const int lx = threadIdx.x, ly = threadIdx.y;
#pragma unroll
    for (int i = 0; i < 32; i += 8)
        t[ly + i][lx] = src[(size_t)(r0 + ly + i) * C + c0 + lx];
    __syncthreads();
#pragma unroll
    for (int i = 0; i < 32; i += 8)
        dst[(size_t)(c0 + ly + i) * R + r0 + lx] = __float2bfloat16(t[lx][ly + i]);
}

// ============================================================
// Kernel 1 (FUSED): bf16 QKV GEMM + rotary + attention + residual + LN1
// 256 thr / 8 warps (2x4), CTA = 64 rows = 2 locations.
// Single-stage: A(64x128 bf16, cvt in-flight) + 3 B tiles(128x128 bf16).
// smem words: A 64*68=4352 | B[w] 128*68=8704 each -> 30464 words (119 KB)
// outputs (Kbuf/Vbuf/Qbuf fp32 64*132 = 25344 floats) overlay staging.
// ============================================================
#define A_W 68
#define FB_OFF(w) (4352 + (w)*8704)
#define M_SMEM_WORDS 30464
#define M_SMEM_BYTES (M_SMEM_WORDS*4)
#define FP 132

__global__ __launch_bounds__(256)
void k_fused_attn(const float* __restrict__ x,
                  const float* __restrict__ bq, const float* __restrict__ bk,
                  const float* __restrict__ bv,
                  const float* __restrict__ ln1g, const float* __restrict__ ln1b)
{
    extern __shared__ unsigned sm_u[];
    float* smf = (float*)sm_u;
    __shared__ float sinT[SEQ][8];
    __shared__ float cosT[SEQ][8];

    float* Kbuf = smf;
    float* Vbuf = smf + 8448;
    float* Qbuf = smf + 16896;

    const int tid = threadIdx.x;
    const int warp = tid >> 5, lane = tid & 31;
    const int wm = warp >> 2, wn = warp & 3;
    const int g = lane >> 2, t = lane & 3;
    const int m0 = blockIdx.x * 64;

    if (tid < SEQ * 8) {
        const int s = tid >> 3, j = tid & 7;
        const float ang = powf(10000.0f, -(float)j / 7.0f);
        float sv, cv;
        sincosf((float)s * ang, &sv, &cv);
        sinT[s][j] = sv;
        cosT[s][j] = cv;
    }

    // ---- stage B tiles (bf16 weights, n-major) via cp.async ----
    {
        const __nv_bfloat16* Ws[3] = { g_wktb, g_wvtb, g_wqtb };
#pragma unroll
        for (int w = 0; w < 3; w++) {
#pragma unroll
            for (int j = 0; j < 8; j++) {
                const int i = tid + j * 256;
                const int row = i >> 4, u = i & 15;
                cp16(&sm_u[FB_OFF(w) + row * A_W + u * 4],
                     &Ws[w][(size_t)row * CDIM + u * 8]);
            }
        }
        cp_commit();
    }
    // ---- stage A: load x fp32 (gathered), convert to bf16, STS ----
    {
        const int row = tid >> 2;
        const int seg = tid & 3;          // 16 words = 32 floats
        const int r = m0 + row;
        const float* src = &x[(size_t)(r & 31) * (NLOC * CDIM)
                              + (size_t)(r >> 5) * CDIM + seg * 32];
        unsigned* dstw = &sm_u[row * A_W + seg * 16];
#pragma unroll
        for (int q = 0; q < 8; q++) {
            float4 v = *(const float4*)(src + q * 4);
            __nv_bfloat162 b0 = __floats2bfloat162_rn(v.x, v.y);
            __nv_bfloat162 b1 = __floats2bfloat162_rn(v.z, v.w);
            dstw[q * 2]     = *(unsigned*)&b0;
            dstw[q * 2 + 1] = *(unsigned*)&b1;
        }
    }
    cp_wait<0>();
    __syncthreads();

    // ---- single-pass bf16 mma: 3 weights x warp tile 32x32 ----
    float acc[3][2][4][4];
#pragma unroll
    for (int w = 0; w < 3; w++)
#pragma unroll
        for (int i = 0; i < 2; i++)
#pragma unroll
            for (int j = 0; j < 4; j++)
#pragma unroll
                for (int q = 0; q < 4; q++) acc[w][i][j][q] = 0.0f;

#pragma unroll
    for (int s = 0; s < 8; s++) {
        unsigned aw[2][4];
#pragma unroll
        for (int mf = 0; mf < 2; mf++) {
            const int row = wm * 32 + mf * 16 + g;
            aw[mf][0] = sm_u[row * A_W + s * 8 + t];
            aw[mf][1] = sm_u[(row + 8) * A_W + s * 8 + t];
            aw[mf][2] = sm_u[row * A_W + s * 8 + t + 4];
            aw[mf][3] = sm_u[(row + 8) * A_W + s * 8 + t + 4];
        }
#pragma unroll
        for (int w = 0; w < 3; w++) {
            const unsigned* Bs = &sm_u[FB_OFF(w)];
#pragma unroll
            for (int nf = 0; nf < 4; nf++) {
                const int n = wn * 32 + nf * 8 + g;
                unsigned bw[2];
                bw[0] = Bs[n * A_W + s * 8 + t];
                bw[1] = Bs[n * A_W + s * 8 + t + 4];
#pragma unroll
                for (int mf = 0; mf < 2; mf++)
                    mma16(acc[w][mf][nf], aw[mf], bw);
            }
        }
    }
    __syncthreads();   // staging dead; outputs may overwrite

    // ---- epilogue: acc + bias -> K/V/Q fp32 smem tiles ----
    {
        const float* biases[3] = { bk, bv, bq };
        float* dsts[3] = { Kbuf, Vbuf, Qbuf };
#pragma unroll
        for (int w = 0; w < 3; w++) {
            float* dst = dsts[w];
            const float* BIAS = biases[w];
#pragma unroll
            for (int nf = 0; nf < 4; nf++) {
                const int col = wn * 32 + nf * 8 + 2 * t;
                const float2 bv2 = *(const float2*)&BIAS[col];
#pragma unroll
                for (int mf = 0; mf < 2; mf++) {
                    const int row0 = wm * 32 + mf * 16 + g;
                    float2 o0, o1;
                    o0.x = acc[w][mf][nf][0] + bv2.x; o0.y = acc[w][mf][nf][1] + bv2.y;
                    o1.x = acc[w][mf][nf][2] + bv2.x; o1.y = acc[w][mf][nf][3] + bv2.y;
                    *(float2*)&dst[row0 * FP + col] = o0;
                    *(float2*)&dst[(row0 + 8) * FP + col] = o1;
                }
            }
        }
    }
    __syncthreads();

    // ---- in-place rotary on Qbuf and Kbuf ----
#pragma unroll
    for (int task = tid; task < 64 * NHEAD; task += 256) {
        const int row = task >> 3, h = task & 7;
        const int s = row & 31;
        float tq[HD], tk[HD];
#pragma unroll
        for (int d4 = 0; d4 < 4; d4++) {
            *(float4*)&tq[d4 * 4] = *(const float4*)&Qbuf[row * FP + h * 16 + d4 * 4];
            *(float4*)&tk[d4 * 4] = *(const float4*)&Kbuf[row * FP + h * 16 + d4 * 4];
        }
        float rq[HD], rk[HD];
#pragma unroll
        for (int d = 0; d < HD; d++) {
            const float sv = sinT[s][d >> 1];
            const float cv = cosT[s][d >> 1];
            const int pc = (d < 8) ? (2 * d + 1) : (2 * d - 16);
            const float sgn = (d < 8) ? -1.0f : 1.0f;
            rq[d] = tq[d] * cv + sgn * tq[pc] * sv;
            rk[d] = tk[d] * cv + sgn * tk[pc] * sv;
        }
#pragma unroll
        for (int d4 = 0; d4 < 4; d4++) {
            *(float4*)&Qbuf[row * FP + h * 16 + d4 * 4] = *(const float4*)&rq[d4 * 4];
            *(float4*)&Kbuf[row * FP + h * 16 + d4 * 4] = *(const float4*)&rk[d4 * 4];
        }
    }
    __syncthreads();

    // ---- attention: warp w -> head w, locations 0 and 1 ----
    const int h = warp;
    const float decay = log1pf(-exp2f(-(1.0f + 3.0f * (float)h / 8.0f)));

#pragma unroll
    for (int l = 0; l < 2; l++) {
        const int qrow = l * 32 + lane;

        u64t q2[8];
        {
            const float* qp = &Qbuf[qrow * FP + h * 16];
            ulonglong2 qa = *(const ulonglong2*)(qp);
            ulonglong2 qb = *(const ulonglong2*)(qp + 4);
            ulonglong2 qc = *(const ulonglong2*)(qp + 8);
            ulonglong2 qd = *(const ulonglong2*)(qp + 12);
            q2[0] = qa.x; q2[1] = qa.y; q2[2] = qb.x; q2[3] = qb.y;
            q2[4] = qc.x; q2[5] = qc.y; q2[6] = qd.x; q2[7] = qd.y;
        }

        float p[SEQ];
        float mx = -1e30f;
#pragma unroll
        for (int j = 0; j < SEQ; j++) {
            const float* kp = &Kbuf[(l * 32 + j) * FP + h * 16];
            ulonglong2 ka = *(const ulonglong2*)(kp);
            ulonglong2 kb = *(const ulonglong2*)(kp + 4);
            ulonglong2 kc = *(const ulonglong2*)(kp + 8);
            ulonglong2 kd = *(const ulonglong2*)(kp + 12);
            u64t s2 = 0ull;
            fma2(s2, q2[0], ka.x); fma2(s2, q2[1], ka.y);
            fma2(s2, q2[2], kb.x); fma2(s2, q2[3], kb.y);
            fma2(s2, q2[4], kc.x); fma2(s2, q2[5], kc.y);
            fma2(s2, q2[6], kd.x); fma2(s2, q2[7], kd.y);
            float lo, hi;
            upk2(s2, lo, hi);
            const float dot = lo + hi + fabsf((float)(lane - j)) * decay;
            p[j] = dot;
            mx = fmaxf(mx, dot);
        }
        float sum = 0.0f;
#pragma unroll
        for (int j = 0; j < SEQ; j++) { p[j] = expf(p[j] - mx); sum += p[j]; }
        const float inv = 1.0f / sum;

        u64t o2[8];
#pragma unroll
        for (int i = 0; i < 8; i++) o2[i] = 0ull;
#pragma unroll
        for (int j = 0; j < SEQ; j++) {
            const float* vp = &Vbuf[(l * 32 + j) * FP + h * 16];
            ulonglong2 va = *(const ulonglong2*)(vp);
            ulonglong2 vb = *(const ulonglong2*)(vp + 4);
            ulonglong2 vc = *(const ulonglong2*)(vp + 8);
            ulonglong2 vd = *(const ulonglong2*)(vp + 12);
            const u64t pj2 = pk2(p[j], p[j]);
            fma2(o2[0], va.x, pj2); fma2(o2[1], va.y, pj2);
            fma2(o2[2], vb.x, pj2); fma2(o2[3], vb.y, pj2);
            fma2(o2[4], vc.x, pj2); fma2(o2[5], vc.y, pj2);
            fma2(o2[6], vd.x, pj2); fma2(o2[7], vd.y, pj2);
        }
        float o[HD];
#pragma unroll
        for (int i = 0; i < 8; i++) {
            float lo, hi;
            upk2(o2[i], lo, hi);
            o[2 * i] = lo * inv;
            o[2 * i + 1] = hi * inv;
        }
#pragma unroll
        for (int d4 = 0; d4 < 4; d4++)
            *(float4*)&Qbuf[qrow * FP + h * 16 + d4 * 4] = *(const float4*)&o[d4 * 4];
    }
    __syncthreads();

    // ---- residual + LN1 -> g_x1 (fp32) + g_x1b (bf16) ----
#pragma unroll
    for (int rr = 0; rr < 8; rr++) {
        const int row = warp * 8 + rr;
        const int r = m0 + row;
        const int c = lane * 4;
        float4 ov = *(const float4*)&Qbuf[row * FP + c];
        float4 xv = *(const float4*)&x[(size_t)(r & 31) * (NLOC * CDIM) + (size_t)(r >> 5) * CDIM + c];
        float v0 = ov.x + xv.x, v1 = ov.y + xv.y, v2 = ov.z + xv.z, v3 = ov.w + xv.w;
        float sum = v0 + v1 + v2 + v3;
        float sq  = v0 * v0 + v1 * v1 + v2 * v2 + v3 * v3;
#pragma unroll
        for (int off = 16; off > 0; off >>= 1) {
            sum += __shfl_xor_sync(0xffffffffu, sum, off);
            sq  += __shfl_xor_sync(0xffffffffu, sq,  off);
        }
        const float mu  = sum * (1.0f / 128.0f);
        const float var = sq * (1.0f / 128.0f) - mu * mu;
        const float wnr = rsqrtf(var + 1e-5f);
        float4 g4 = *(const float4*)&ln1g[c];
        float4 b4 = *(const float4*)&ln1b[c];
        float4 o;
        o.x = (v0 - mu) * wnr * g4.x + b4.x;
        o.y = (v1 - mu) * wnr * g4.y + b4.y;
        o.z = (v2 - mu) * wnr * g4.z + b4.z;
        o.w = (v3 - mu) * wnr * g4.w + b4.w;
        *(float4*)&g_x1[(size_t)r * CDIM + c] = o;
        __nv_bfloat162* bd = (__nv_bfloat162*)&g_x1b[(size_t)r * CDIM + c];
        bd[0] = __floats2bfloat162_rn(o.x, o.y);
        bd[1] = __floats2bfloat162_rn(o.z, o.w);
    }
}

// ============================================================
// Kernel 2: FFN1 bf16  H = relu(x1b @ w1 + b1)  (unchanged R9)
// ============================================================
#define F1W 68
#define F1_B0 8704
#define F1_B1 17408
#define F1_SMEM_BYTES (26112*4)

__device__ __forceinline__ void f1_stage_b(unsigned* sm_u, int dstoff, int nt, int tid)
{
#pragma unroll
    for (int j = 0; j < 8; j++) {
        const int i = tid + j * 256;
        const int row = i >> 4, u = i & 15;
        cp16(&sm_u[dstoff + row * F1W + u * 4],
             &g_w1tb[(size_t)(nt * 128 + row) * CDIM + u * 8]);
    }
    cp_commit();
}

__global__ __launch_bounds__(256, 2)
void k_ffn1_bf(const float* __restrict__ b1)
{
    extern __shared__ unsigned sm_u[];
    const int tid = threadIdx.x;
    const int warp = tid >> 5, lane = tid & 31;
    const int wm = warp >> 2, wn = warp & 3;
    const int g = lane >> 2, t = lane & 3;
    const int m0 = blockIdx.x * 128;

#pragma unroll
    for (int j = 0; j < 8; j++) {
        const int i = tid + j * 256;
        const int row = i >> 4, u = i & 15;
        cp16(&sm_u[row * F1W + u * 4],
             &g_x1b[(size_t)(m0 + row) * CDIM + u * 8]);
    }
#pragma unroll
    for (int j = 0; j < 8; j++) {
        const int i = tid + j * 256;
        const int row = i >> 4, u = i & 15;
        cp16(&sm_u[F1_B0 + row * F1W + u * 4],
             &g_w1tb[(size_t)row * CDIM + u * 8]);
    }
    cp_commit();
    f1_stage_b(sm_u, F1_B1, 1, tid);
    cp_wait<1>();
    __syncthreads();

#pragma unroll 1
    for (int nt = 0; nt < 4; nt++) {
        const unsigned* Bs = &sm_u[(nt & 1) ? F1_B1 : F1_B0];
        float acc[4][4][4];
#pragma unroll
        for (int i = 0; i < 4; i++)
#pragma unroll
            for (int j = 0; j < 4; j++)
#pragma unroll
                for (int q = 0; q < 4; q++) acc[i][j][q] = 0.0f;

#pragma unroll
        for (int s = 0; s < 8; s++) {
            unsigned aw[4][4];
#pragma unroll
            for (int mf = 0; mf < 4; mf++) {
                const int row = wm * 64 + mf * 16 + g;
                aw[mf][0] = sm_u[row * F1W + s * 8 + t];
                aw[mf][1] = sm_u[(row + 8) * F1W + s * 8 + t];
                aw[mf][2] = sm_u[row * F1W + s * 8 + t + 4];
                aw[mf][3] = sm_u[(row + 8) * F1W + s * 8 + t + 4];
            }
#pragma unroll
            for (int nf = 0; nf < 4; nf++) {
                const int n = wn * 32 + nf * 8 + g;
                unsigned bw[2];
                bw[0] = Bs[n * F1W + s * 8 + t];
                bw[1] = Bs[n * F1W + s * 8 + t + 4];
#pragma unroll
                for (int mf = 0; mf < 4; mf++)
                    mma16(acc[mf][nf], aw[mf], bw);
            }
        }

#pragma unroll
        for (int nf = 0; nf < 4; nf++) {
            const int col = wn * 32 + nf * 8 + 2 * t;
            const float2 bb = *(const float2*)&b1[nt * 128 + col];
#pragma unroll
            for (int mf = 0; mf < 4; mf++) {
                const int r0 = m0 + wm * 64 + mf * 16 + g;
                float h00 = fmaxf(acc[mf][nf][0] + bb.x, 0.0f);
                float h01 = fmaxf(acc[mf][nf][1] + bb.y, 0.0f);
                float h10 = fmaxf(acc[mf][nf][2] + bb.x, 0.0f);
                float h11 = fmaxf(acc[mf][nf][3] + bb.y, 0.0f);
                *(__nv_bfloat162*)&g_hb[(size_t)r0 * FFND + nt * 128 + col] =
                    __floats2bfloat162_rn(h00, h01);
                *(__nv_bfloat162*)&g_hb[(size_t)(r0 + 8) * FFND + nt * 128 + col] =
                    __floats2bfloat162_rn(h10, h11);
            }
        }
        __syncthreads();
        if (nt + 2 < 4) {
            f1_stage_b(sm_u, (nt & 1) ? F1_B1 : F1_B0, nt + 2, tid);
            cp_wait<1>();
            __syncthreads();
        } else if (nt + 1 < 4) {
            cp_wait<0>();
            __syncthreads();
        }
    }
}

// ============================================================
// Kernel 3: FFN2 bf16 + residual + LN2 + transposed output (unchanged R9)
// ============================================================
#define F2W 36
#define F2_A1 4608
#define F2_B0 9216
#define F2_B1 13824
#define F2_SMEM_BYTES (18432*4)
#define TP 132

__device__ __forceinline__ void f2_stage(unsigned* sm_u, int m0, int c, int buf, int tid)
{
    const int aoff = buf ? F2_A1 : 0;
    const int boff = buf ? F2_B1 : F2_B0;
#pragma unroll
    for (int j = 0; j < 4; j++) {
        const int i = tid + j * 256;
        const int row = i >> 3, u = i & 7;
        cp16(&sm_u[aoff + row * F2W + u * 4],
             &g_hb[(size_t)(m0 + row) * FFND + c * 64 + u * 8]);
        cp16(&sm_u[boff + row * F2W + u * 4],
             &g_w2tb[(size_t)row * FFND + c * 64 + u * 8]);
    }
    cp_commit();
}

__global__ __launch_bounds__(256, 2)
void k_ffn2_bf(const float* __restrict__ b2,
               const float* __restrict__ ln2g, const float* __restrict__ ln2b,
               float* __restrict__ out)
{
    extern __shared__ unsigned sm_u[];
    const int tid = threadIdx.x;
    const int warp = tid >> 5, lane = tid & 31;
    const int wm = warp >> 2, wn = warp & 3;
    const int g = lane >> 2, t = lane & 3;
    const int m0 = blockIdx.x * 128;

    float acc[4][4][4];
#pragma unroll
    for (int i = 0; i < 4; i++)
#pragma unroll
        for (int j = 0; j < 4; j++)
#pragma unroll
            for (int q = 0; q < 4; q++) acc[i][j][q] = 0.0f;

    f2_stage(sm_u, m0, 0, 0, tid);
    f2_stage(sm_u, m0, 1, 1, tid);
    cp_wait<1>();
    __syncthreads();

#pragma unroll 1
    for (int c = 0; c < 8; c++) {
        const unsigned* As = &sm_u[(c & 1) ? F2_A1 : 0];
        const unsigned* Bs = &sm_u[(c & 1) ? F2_B1 : F2_B0];
#pragma unroll
        for (int s = 0; s < 4; s++) {
            unsigned aw[4][4];
#pragma unroll
            for (int mf = 0; mf < 4; mf++) {
                const int row = wm * 64 + mf * 16 + g;
                aw[mf][0] = As[row * F2W + s * 8 + t];
                aw[mf][1] = As[(row + 8) * F2W + s * 8 + t];
                aw[mf][2] = As[row * F2W + s * 8 + t + 4];
                aw[mf][3] = As[(row + 8) * F2W + s * 8 + t + 4];
            }
#pragma unroll
            for (int nf = 0; nf < 4; nf++) {
                const int n = wn * 32 + nf * 8 + g;
                unsigned bw[2];
                bw[0] = Bs[n * F2W + s * 8 + t];
                bw[1] = Bs[n * F2W + s * 8 + t + 4];
#pragma unroll
                for (int mf = 0; mf < 4; mf++)
                    mma16(acc[mf][nf], aw[mf], bw);
            }
        }
        __syncthreads();
        if (c + 2 < 8) {
            f2_stage(sm_u, m0, c + 2, c & 1, tid);
            cp_wait<1>();
            __syncthreads();
        } else if (c + 1 < 8) {
            cp_wait<0>();
            __syncthreads();
        }
    }
    __syncthreads();

    float* T = (float*)sm_u;
#pragma unroll
    for (int nf = 0; nf < 4; nf++) {
        const int col = wn * 32 + nf * 8 + 2 * t;
        const float2 bb = *(const float2*)&b2[col];
#pragma unroll
        for (int mf = 0; mf < 4; mf++) {
            const int row0 = wm * 64 + mf * 16 + g;
            float2 o0, o1;
            o0.x = acc[mf][nf][0] + bb.x; o0.y = acc[mf][nf][1] + bb.y;
            o1.x = acc[mf][nf][2] + bb.x; o1.y = acc[mf][nf][3] + bb.y;
            *(float2*)&T[row0 * TP + col] = o0;
            *(float2*)&T[(row0 + 8) * TP + col] = o1;
        }
    }
    __syncthreads();

#pragma unroll
    for (int rr = 0; rr < 16; rr++) {
        const int row = warp * 16 + rr;
        const int r = m0 + row;
        const int c = lane * 4;
        float4 v = *(const float4*)&T[row * TP + c];
        float4 xv = *(const float4*)&g_x1[(size_t)r * CDIM + c];
        float v0 = v.x + xv.x, v1 = v.y + xv.y, v2 = v.z + xv.z, v3 = v.w + xv.w;
        float sum = v0 + v1 + v2 + v3;
        float sq  = v0 * v0 + v1 * v1 + v2 * v2 + v3 * v3;
#pragma unroll
        for (int off = 16; off > 0; off >>= 1) {
            sum += __shfl_xor_sync(0xffffffffu, sum, off);
            sq  += __shfl_xor_sync(0xffffffffu, sq,  off);
        }
        const float mu  = sum * (1.0f / 128.0f);
        const float var = sq * (1.0f / 128.0f) - mu * mu;
        const float wnr = rsqrtf(var + 1e-5f);
        float4 g4 = *(const float4*)&ln2g[c];
        float4 b4 = *(const float4*)&ln2b[c];
        float4 o;
        o.x = (v0 - mu) * wnr * g4.x + b4.x;
        o.y = (v1 - mu) * wnr * g4.y + b4.y;
        o.z = (v2 - mu) * wnr * g4.z + b4.z;
        o.w = (v3 - mu) * wnr * g4.w + b4.w;
        const int nn = r >> 5;
        const int ss = r & 31;
        *(float4*)&out[(size_t)ss * NLOC * CDIM + (size_t)nn * CDIM + c] = o;
    }
}

// ============================================================
extern "C" void kernel_launch(void* const* d_in, const int* in_sizes, int n_in,
                              void* d_out, int out_size)
{
    (void)in_sizes; (void)n_in; (void)out_size;
    const float* x    = (const float*)d_in[0];
    const float* wq   = (const float*)d_in[1];
    const float* bq   = (const float*)d_in[2];
    const float* wk   = (const float*)d_in[3];
    const float* bk   = (const float*)d_in[4];
    const float* wv   = (const float*)d_in[5];
    const float* bv   = (const float*)d_in[6];
    const float* ln1g = (const float*)d_in[7];
    const float* ln1b = (const float*)d_in[8];
    const float* w1   = (const float*)d_in[9];
    const float* b1   = (const float*)d_in[10];
    const float* w2   = (const float*)d_in[11];
    const float* b2   = (const float*)d_in[12];
    const float* ln2g = (const float*)d_in[13];
    const float* ln2b = (const float*)d_in[14];
    float* out = (float*)d_out;

    cudaFuncSetAttribute(k_fused_attn, cudaFuncAttributeMaxDynamicSharedMemorySize, M_SMEM_BYTES);
    cudaFuncSetAttribute(k_ffn1_bf, cudaFuncAttributeMaxDynamicSharedMemorySize, F1_SMEM_BYTES);
    cudaFuncSetAttribute(k_ffn2_bf, cudaFuncAttributeMaxDynamicSharedMemorySize, F2_SMEM_BYTES);

    dim3 tg(16, 16, 5), tb(32, 8);
    k_wtb<<<tg, tb>>>(w1, w2, wq, wk, wv);

    k_fused_attn<<<MROWS / 64, 256, M_SMEM_BYTES>>>(x, bq, bk, bv, ln1g, ln1b);

    k_ffn1_bf<<<MROWS / 128, 256, F1_SMEM_BYTES>>>(b1);

    k_ffn2_bf<<<MROWS / 128, 256, F2_SMEM_BYTES>>>(b2, ln2g, ln2b, out);
}

// round 11
// speedup vs baseline: 1.3194x; 1.0567x over previous
#include <cuda_runtime.h>
#include <cuda_bf16.h>
#include <math.h>

#define NLOC 8192
#define SEQ 32
#define CDIM 128
#define NHEAD 8
#define HD 16
#define MROWS (NLOC*SEQ)   // 262144
#define FFND 512

// -------- scratch (static device globals; no runtime allocation) --------
__device__ float g_x1[(size_t)MROWS * CDIM];            // fp32 residual
__device__ __nv_bfloat16 g_x1b[(size_t)MROWS * CDIM];   // ffn1 A operand
__device__ __nv_bfloat16 g_hb[(size_t)MROWS * FFND];    // ffn2 A operand
__device__ __nv_bfloat16 g_w1tb[(size_t)FFND * CDIM];   // w1^T bf16 [512][128]
__device__ __nv_bfloat16 g_w2tb[(size_t)CDIM * FFND];   // w2^T bf16 [128][512]
__device__ __nv_bfloat16 g_wqtb[(size_t)CDIM * CDIM];   // wq^T bf16 [n][k]
__device__ __nv_bfloat16 g_wktb[(size_t)CDIM * CDIM];
__device__ __nv_bfloat16 g_wvtb[(size_t)CDIM * CDIM];

// ======================= mma / cp.async helpers =======================
__device__ __forceinline__ void mma16(float* c, const unsigned* a, const unsigned* b) {
    asm volatile(
        "mma.sync.aligned.m16n8k16.row.col.f32.bf16.bf16.f32 "
        "{%0,%1,%2,%3}, {%4,%5,%6,%7}, {%8,%9}, {%0,%1,%2,%3};"
        : "+f"(c[0]), "+f"(c[1]), "+f"(c[2]), "+f"(c[3])
        : "r"(a[0]), "r"(a[1]), "r"(a[2]), "r"(a[3]),
          "r"(b[0]), "r"(b[1]));
}

__device__ __forceinline__ void cp16(void* s, const void* g) {
    unsigned saddr = (unsigned)__cvta_generic_to_shared(s);
    asm volatile("cp.async.cg.shared.global [%0], [%1], 16;" :: "r"(saddr), "l"(g));
}
__device__ __forceinline__ void cp_commit() {
    asm volatile("cp.async.commit_group;");
}
template<int N>
__device__ __forceinline__ void cp_wait() {
    asm volatile("cp.async.wait_group %0;" :: "n"(N));
}

// packed f32x2
typedef unsigned long long u64t;
__device__ __forceinline__ u64t pk2(float lo, float hi) {
    u64t r; asm("mov.b64 %0,{%1,%2};" : "=l"(r) : "f"(lo), "f"(hi)); return r;
}
__device__ __forceinline__ void upk2(u64t v, float& lo, float& hi) {
    asm("mov.b64 {%0,%1},%2;" : "=f"(lo), "=f"(hi) : "l"(v));
}
__device__ __forceinline__ void fma2(u64t& d, u64t a, u64t b) {
    asm("fma.rn.f32x2 %0,%1,%2,%0;" : "+l"(d) : "l"(a), "l"(b));
}

// ============================================================
// Kernel 0: transpose + convert all weights to bf16 (n-major)
// ============================================================
__global__ void k_wtb(const float* __restrict__ w1, const float* __restrict__ w2,
                      const float* __restrict__ wq, const float* __restrict__ wk,
                      const float* __restrict__ wv)
{
    __shared__ float t[32][33];
    const int which = blockIdx.z;
    const float* srcs[5] = { w1, w2, wq, wk, wv };
    __nv_bfloat16* dsts[5] = { g_w1tb, g_w2tb, g_wqtb, g_wktb, g_wvtb };
    const int Rs[5] = { 128, 512, 128, 128, 128 };
    const int Cs[5] = { 512, 128, 128, 128, 128 };
    const float* src = srcs[which];
    __nv_bfloat16* dst = dsts[which];
    const int R = Rs[which], C = Cs[which];
    const int r0 = blockIdx.y * 32, c0 = blockIdx.x * 32;
    if (r0 >= R || c0 >= C) return;
    const int lx = threadIdx.x, ly = threadIdx.y;
#pragma unroll
    for (int i = 0; i < 32; i += 8)
        t[ly + i][lx] = src[(size_t)(r0 + ly + i) * C + c0 + lx];
    __syncthreads();
#pragma unroll
    for (int i = 0; i < 32; i += 8)
        dst[(size_t)(c0 + ly + i) * R + r0 + lx] = __float2bfloat16(t[lx][ly + i]);
}

// ============================================================
// Kernel 1 (FUSED): bf16 QKV GEMM (two-pass, 2-B-tile staging)
// + rotary + attention + residual + LN1.
// 256 thr / 8 warps (2x4), CTA = 64 rows = 2 locations, 2 CTAs/SM.
// smem words: staging A 4352 | B0 8704 | B1 8704 = 21760
//             outputs K/V/Q fp32 3*8448 = 25344  (dynamic = 25344 words)
// ============================================================
#define A_W 68
#define FB0 4352
#define FB1 13056
#define M_SMEM_WORDS 25344
#define M_SMEM_BYTES (M_SMEM_WORDS*4)   // 101376 B
#define FP 132

__device__ __forceinline__ void f_stage_w(unsigned* sm_u, int dstoff,
                                          const __nv_bfloat16* W, int tid)
{
#pragma unroll
    for (int j = 0; j < 8; j++) {
        const int i = tid + j * 256;
        const int row = i >> 4, u = i & 15;
        cp16(&sm_u[dstoff + row * A_W + u * 4], &W[(size_t)row * CDIM + u * 8]);
    }
    cp_commit();
}

// one weight's 64x128 GEMM pass: acc[2][4][4]
__device__ __forceinline__ void f_mma_pass(const unsigned* __restrict__ sm_u,
                                           const unsigned* __restrict__ Bs,
                                           float acc[2][4][4],
                                           int wm, int wn, int g, int t)
{
#pragma unroll
    for (int s = 0; s < 8; s++) {
        unsigned aw[2][4];
#pragma unroll
        for (int mf = 0; mf < 2; mf++) {
            const int row = wm * 32 + mf * 16 + g;
            aw[mf][0] = sm_u[row * A_W + s * 8 + t];
            aw[mf][1] = sm_u[(row + 8) * A_W + s * 8 + t];
            aw[mf][2] = sm_u[row * A_W + s * 8 + t + 4];
            aw[mf][3] = sm_u[(row + 8) * A_W + s * 8 + t + 4];
        }
#pragma unroll
        for (int nf = 0; nf < 4; nf++) {
            const int n = wn * 32 + nf * 8 + g;
            unsigned bw[2];
            bw[0] = Bs[n * A_W + s * 8 + t];
            bw[1] = Bs[n * A_W + s * 8 + t + 4];
#pragma unroll
            for (int mf = 0; mf < 2; mf++)
                mma16(acc[mf][nf], aw[mf], bw);
        }
    }
}

// two-weight pass sharing A fragments: accX, accY
__device__ __forceinline__ void f_mma_pass2(const unsigned* __restrict__ sm_u,
                                            const unsigned* __restrict__ Bs0,
                                            const unsigned* __restrict__ Bs1,
                                            float acc0[2][4][4], float acc1[2][4][4],
                                            int wm, int wn, int g, int t)
{
#pragma unroll
    for (int s = 0; s < 8; s++) {
        unsigned aw[2][4];
#pragma unroll
        for (int mf = 0; mf < 2; mf++) {
            const int row = wm * 32 + mf * 16 + g;
            aw[mf][0] = sm_u[row * A_W + s * 8 + t];
            aw[mf][1] = sm_u[(row + 8) * A_W + s * 8 + t];
            aw[mf][2] = sm_u[row * A_W + s * 8 + t + 4];
            aw[mf][3] = sm_u[(row + 8) * A_W + s * 8 + t + 4];
        }
#pragma unroll
        for (int nf = 0; nf < 4; nf++) {
            const int n = wn * 32 + nf * 8 + g;
            unsigned bw0[2], bw1[2];
            bw0[0] = Bs0[n * A_W + s * 8 + t];
            bw0[1] = Bs0[n * A_W + s * 8 + t + 4];
            bw1[0] = Bs1[n * A_W + s * 8 + t];
            bw1[1] = Bs1[n * A_W + s * 8 + t + 4];
#pragma unroll
            for (int mf = 0; mf < 2; mf++) {
                mma16(acc0[mf][nf], aw[mf], bw0);
                mma16(acc1[mf][nf], aw[mf], bw1);
            }
        }
    }
}

__global__ __launch_bounds__(256, 2)
void k_fused_attn(const float* __restrict__ x,
                  const float* __restrict__ bq, const float* __restrict__ bk,
                  const float* __restrict__ bv,
                  const float* __restrict__ ln1g, const float* __restrict__ ln1b)
{
    extern __shared__ unsigned sm_u[];
    float* smf = (float*)sm_u;
    __shared__ float sinT[SEQ][8];
    __shared__ float cosT[SEQ][8];

    float* Kbuf = smf;
    float* Vbuf = smf + 8448;
    float* Qbuf = smf + 16896;

    const int tid = threadIdx.x;
    const int warp = tid >> 5, lane = tid & 31;
    const int wm = warp >> 2, wn = warp & 3;
    const int g = lane >> 2, t = lane & 3;
    const int m0 = blockIdx.x * 64;

    if (tid < SEQ * 8) {
        const int s = tid >> 3, j = tid & 7;
        const float ang = powf(10000.0f, -(float)j / 7.0f);
        float sv, cv;
        sincosf((float)s * ang, &sv, &cv);
        sinT[s][j] = sv;
        cosT[s][j] = cv;
    }

    // ---- stage B_k, B_v via cp.async; A via cvt+STS ----
    f_stage_w(sm_u, FB0, g_wktb, tid);
    f_stage_w(sm_u, FB1, g_wvtb, tid);
    {
        const int row = tid >> 2;
        const int seg = tid & 3;
        const int r = m0 + row;
        const float* src = &x[(size_t)(r & 31) * (NLOC * CDIM)
                              + (size_t)(r >> 5) * CDIM + seg * 32];
        unsigned* dstw = &sm_u[row * A_W + seg * 16];
#pragma unroll
        for (int q = 0; q < 8; q++) {
            float4 v = *(const float4*)(src + q * 4);
            __nv_bfloat162 b0 = __floats2bfloat162_rn(v.x, v.y);
            __nv_bfloat162 b1 = __floats2bfloat162_rn(v.z, v.w);
            dstw[q * 2]     = *(unsigned*)&b0;
            dstw[q * 2 + 1] = *(unsigned*)&b1;
        }
    }
    cp_wait<0>();
    __syncthreads();

    // ---- pass 1: K and V accumulators (shared A fragments) ----
    float acc[3][2][4][4];
#pragma unroll
    for (int w = 0; w < 3; w++)
#pragma unroll
        for (int i = 0; i < 2; i++)
#pragma unroll
            for (int j = 0; j < 4; j++)
#pragma unroll
                for (int q = 0; q < 4; q++) acc[w][i][j][q] = 0.0f;

    f_mma_pass2(sm_u, &sm_u[FB0], &sm_u[FB1], acc[0], acc[1], wm, wn, g, t);
    __syncthreads();   // all warps done with B_k slot

    // ---- stage B_q over B_k, pass 2: Q accumulator ----
    f_stage_w(sm_u, FB0, g_wqtb, tid);
    cp_wait<0>();
    __syncthreads();
    f_mma_pass(sm_u, &sm_u[FB0], acc[2], wm, wn, g, t);
    __syncthreads();   // staging dead; outputs may overwrite

    // ---- epilogue: acc + bias -> K/V/Q fp32 smem tiles ----
    {
        const float* biases[3] = { bk, bv, bq };
        float* dsts[3] = { Kbuf, Vbuf, Qbuf };
#pragma unroll
        for (int w = 0; w < 3; w++) {
            float* dst = dsts[w];
            const float* BIAS = biases[w];
#pragma unroll
            for (int nf = 0; nf < 4; nf++) {
                const int col = wn * 32 + nf * 8 + 2 * t;
                const float2 bv2 = *(const float2*)&BIAS[col];
#pragma unroll
                for (int mf = 0; mf < 2; mf++) {
                    const int row0 = wm * 32 + mf * 16 + g;
                    float2 o0, o1;
                    o0.x = acc[w][mf][nf][0] + bv2.x; o0.y = acc[w][mf][nf][1] + bv2.y;
                    o1.x = acc[w][mf][nf][2] + bv2.x; o1.y = acc[w][mf][nf][3] + bv2.y;
                    *(float2*)&dst[row0 * FP + col] = o0;
                    *(float2*)&dst[(row0 + 8) * FP + col] = o1;
                }
            }
        }
    }
    __syncthreads();

    // ---- in-place rotary on Qbuf and Kbuf ----
#pragma unroll
    for (int task = tid; task < 64 * NHEAD; task += 256) {
        const int row = task >> 3, h = task & 7;
        const int s = row & 31;
        float tq[HD], tk[HD];
#pragma unroll
        for (int d4 = 0; d4 < 4; d4++) {
            *(float4*)&tq[d4 * 4] = *(const float4*)&Qbuf[row * FP + h * 16 + d4 * 4];
            *(float4*)&tk[d4 * 4] = *(const float4*)&Kbuf[row * FP + h * 16 + d4 * 4];
        }
        float rq[HD], rk[HD];
#pragma unroll
        for (int d = 0; d < HD; d++) {
            const float sv = sinT[s][d >> 1];
            const float cv = cosT[s][d >> 1];
            const int pc = (d < 8) ? (2 * d + 1) : (2 * d - 16);
            const float sgn = (d < 8) ? -1.0f : 1.0f;
            rq[d] = tq[d] * cv + sgn * tq[pc] * sv;
            rk[d] = tk[d] * cv + sgn * tk[pc] * sv;
        }
#pragma unroll
        for (int d4 = 0; d4 < 4; d4++) {
            *(float4*)&Qbuf[row * FP + h * 16 + d4 * 4] = *(const float4*)&rq[d4 * 4];
            *(float4*)&Kbuf[row * FP + h * 16 + d4 * 4] = *(const float4*)&rk[d4 * 4];
        }
    }
    __syncthreads();

    // ---- attention: warp w -> head w, locations 0 and 1 ----
    const int h = warp;
    const float decay = log1pf(-exp2f(-(1.0f + 3.0f * (float)h / 8.0f)));

#pragma unroll
    for (int l = 0; l < 2; l++) {
        const int qrow = l * 32 + lane;

        u64t q2[8];
        {
            const float* qp = &Qbuf[qrow * FP + h * 16];
            ulonglong2 qa = *(const ulonglong2*)(qp);
            ulonglong2 qb = *(const ulonglong2*)(qp + 4);
            ulonglong2 qc = *(const ulonglong2*)(qp + 8);
            ulonglong2 qd = *(const ulonglong2*)(qp + 12);
            q2[0] = qa.x; q2[1] = qa.y; q2[2] = qb.x; q2[3] = qb.y;
            q2[4] = qc.x; q2[5] = qc.y; q2[6] = qd.x; q2[7] = qd.y;
        }

        float p[SEQ];
        float mx = -1e30f;
#pragma unroll
        for (int j = 0; j < SEQ; j++) {
            const float* kp = &Kbuf[(l * 32 + j) * FP + h * 16];
            ulonglong2 ka = *(const ulonglong2*)(kp);
            ulonglong2 kb = *(const ulonglong2*)(kp + 4);
            ulonglong2 kc = *(const ulonglong2*)(kp + 8);
            ulonglong2 kd = *(const ulonglong2*)(kp + 12);
            u64t s2 = 0ull;
            fma2(s2, q2[0], ka.x); fma2(s2, q2[1], ka.y);
            fma2(s2, q2[2], kb.x); fma2(s2, q2[3], kb.y);
            fma2(s2, q2[4], kc.x); fma2(s2, q2[5], kc.y);
            fma2(s2, q2[6], kd.x); fma2(s2, q2[7], kd.y);
            float lo, hi;
            upk2(s2, lo, hi);
            const float dot = lo + hi + fabsf((float)(lane - j)) * decay;
            p[j] = dot;
            mx = fmaxf(mx, dot);
        }
        float sum = 0.0f;
#pragma unroll
        for (int j = 0; j < SEQ; j++) { p[j] = expf(p[j] - mx); sum += p[j]; }
        const float inv = 1.0f / sum;

        u64t o2[8];
#pragma unroll
        for (int i = 0; i < 8; i++) o2[i] = 0ull;
#pragma unroll
        for (int j = 0; j < SEQ; j++) {
            const float* vp = &Vbuf[(l * 32 + j) * FP + h * 16];
            ulonglong2 va = *(const ulonglong2*)(vp);
            ulonglong2 vb = *(const ulonglong2*)(vp + 4);
            ulonglong2 vc = *(const ulonglong2*)(vp + 8);
            ulonglong2 vd = *(const ulonglong2*)(vp + 12);
            const u64t pj2 = pk2(p[j], p[j]);
            fma2(o2[0], va.x, pj2); fma2(o2[1], va.y, pj2);
            fma2(o2[2], vb.x, pj2); fma2(o2[3], vb.y, pj2);
            fma2(o2[4], vc.x, pj2); fma2(o2[5], vc.y, pj2);
            fma2(o2[6], vd.x, pj2); fma2(o2[7], vd.y, pj2);
        }
        float o[HD];
#pragma unroll
        for (int i = 0; i < 8; i++) {
            float lo, hi;
            upk2(o2[i], lo, hi);
            o[2 * i] = lo * inv;
            o[2 * i + 1] = hi * inv;
        }
#pragma unroll
        for (int d4 = 0; d4 < 4; d4++)
            *(float4*)&Qbuf[qrow * FP + h * 16 + d4 * 4] = *(const float4*)&o[d4 * 4];
    }
    __syncthreads();

    // ---- residual + LN1 -> g_x1 (fp32) + g_x1b (bf16) ----
#pragma unroll
    for (int rr = 0; rr < 8; rr++) {
        const int row = warp * 8 + rr;
        const int r = m0 + row;
        const int c = lane * 4;
        float4 ov = *(const float4*)&Qbuf[row * FP + c];
        float4 xv = *(const float4*)&x[(size_t)(r & 31) * (NLOC * CDIM) + (size_t)(r >> 5) * CDIM + c];
        float v0 = ov.x + xv.x, v1 = ov.y + xv.y, v2 = ov.z + xv.z, v3 = ov.w + xv.w;
        float sum = v0 + v1 + v2 + v3;
        float sq  = v0 * v0 + v1 * v1 + v2 * v2 + v3 * v3;
#pragma unroll
        for (int off = 16; off > 0; off >>= 1) {
            sum += __shfl_xor_sync(0xffffffffu, sum, off);
            sq  += __shfl_xor_sync(0xffffffffu, sq,  off);
        }
        const float mu  = sum * (1.0f / 128.0f);
        const float var = sq * (1.0f / 128.0f) - mu * mu;
        const float wnr = rsqrtf(var + 1e-5f);
        float4 g4 = *(const float4*)&ln1g[c];
        float4 b4 = *(const float4*)&ln1b[c];
        float4 o;
        o.x = (v0 - mu) * wnr * g4.x + b4.x;
        o.y = (v1 - mu) * wnr * g4.y + b4.y;
        o.z = (v2 - mu) * wnr * g4.z + b4.z;
        o.w = (v3 - mu) * wnr * g4.w + b4.w;
        *(float4*)&g_x1[(size_t)r * CDIM + c] = o;
        __nv_bfloat162* bd = (__nv_bfloat162*)&g_x1b[(size_t)r * CDIM + c];
        bd[0] = __floats2bfloat162_rn(o.x, o.y);
        bd[1] = __floats2bfloat162_rn(o.z, o.w);
    }
}

// ============================================================
// Kernel 2: FFN1 bf16  H = relu(x1b @ w1 + b1)  (unchanged)
// ============================================================
#define F1W 68
#define F1_B0 8704
#define F1_B1 17408
#define F1_SMEM_BYTES (26112*4)

__device__ __forceinline__ void f1_stage_b(unsigned* sm_u, int dstoff, int nt, int tid)
{
#pragma unroll
    for (int j = 0; j < 8; j++) {
        const int i = tid + j * 256;
        const int row = i >> 4, u = i & 15;
        cp16(&sm_u[dstoff + row * F1W + u * 4],
             &g_w1tb[(size_t)(nt * 128 + row) * CDIM + u * 8]);
    }
    cp_commit();
}

__global__ __launch_bounds__(256, 2)
void k_ffn1_bf(const float* __restrict__ b1)
{
    extern __shared__ unsigned sm_u[];
    const int tid = threadIdx.x;
    const int warp = tid >> 5, lane = tid & 31;
    const int wm = warp >> 2, wn = warp & 3;
    const int g = lane >> 2, t = lane & 3;
    const int m0 = blockIdx.x * 128;

#pragma unroll
    for (int j = 0; j < 8; j++) {
        const int i = tid + j * 256;
        const int row = i >> 4, u = i & 15;
        cp16(&sm_u[row * F1W + u * 4],
             &g_x1b[(size_t)(m0 + row) * CDIM + u * 8]);
    }
#pragma unroll
    for (int j = 0; j < 8; j++) {
        const int i = tid + j * 256;
        const int row = i >> 4, u = i & 15;
        cp16(&sm_u[F1_B0 + row * F1W + u * 4],
             &g_w1tb[(size_t)row * CDIM + u * 8]);
    }
    cp_commit();
    f1_stage_b(sm_u, F1_B1, 1, tid);
    cp_wait<1>();
    __syncthreads();

#pragma unroll 1
    for (int nt = 0; nt < 4; nt++) {
        const unsigned* Bs = &sm_u[(nt & 1) ? F1_B1 : F1_B0];
        float acc[4][4][4];
#pragma unroll
        for (int i = 0; i < 4; i++)
#pragma unroll
            for (int j = 0; j < 4; j++)
#pragma unroll
                for (int q = 0; q < 4; q++) acc[i][j][q] = 0.0f;

#pragma unroll
        for (int s = 0; s < 8; s++) {
            unsigned aw[4][4];
#pragma unroll
            for (int mf = 0; mf < 4; mf++) {
                const int row = wm * 64 + mf * 16 + g;
                aw[mf][0] = sm_u[row * F1W + s * 8 + t];
                aw[mf][1] = sm_u[(row + 8) * F1W + s * 8 + t];
                aw[mf][2] = sm_u[row * F1W + s * 8 + t + 4];
                aw[mf][3] = sm_u[(row + 8) * F1W + s * 8 + t + 4];
            }
#pragma unroll
            for (int nf = 0; nf < 4; nf++) {
                const int n = wn * 32 + nf * 8 + g;
                unsigned bw[2];
                bw[0] = Bs[n * F1W + s * 8 + t];
                bw[1] = Bs[n * F1W + s * 8 + t + 4];
#pragma unroll
                for (int mf = 0; mf < 4; mf++)
                    mma16(acc[mf][nf], aw[mf], bw);
            }
        }

#pragma unroll
        for (int nf = 0; nf < 4; nf++) {
            const int col = wn * 32 + nf * 8 + 2 * t;
            const float2 bb = *(const float2*)&b1[nt * 128 + col];
#pragma unroll
            for (int mf = 0; mf < 4; mf++) {
                const int r0 = m0 + wm * 64 + mf * 16 + g;
                float h00 = fmaxf(acc[mf][nf][0] + bb.x, 0.0f);
                float h01 = fmaxf(acc[mf][nf][1] + bb.y, 0.0f);
                float h10 = fmaxf(acc[mf][nf][2] + bb.x, 0.0f);
                float h11 = fmaxf(acc[mf][nf][3] + bb.y, 0.0f);
                *(__nv_bfloat162*)&g_hb[(size_t)r0 * FFND + nt * 128 + col] =
                    __floats2bfloat162_rn(h00, h01);
                *(__nv_bfloat162*)&g_hb[(size_t)(r0 + 8) * FFND + nt * 128 + col] =
                    __floats2bfloat162_rn(h10, h11);
            }
        }
        __syncthreads();
        if (nt + 2 < 4) {
            f1_stage_b(sm_u, (nt & 1) ? F1_B1 : F1_B0, nt + 2, tid);
            cp_wait<1>();
            __syncthreads();
        } else if (nt + 1 < 4) {
            cp_wait<0>();
            __syncthreads();
        }
    }
}

// ============================================================
// Kernel 3: FFN2 bf16 + residual + LN2 + transposed output (unchanged)
// ============================================================
#define F2W 36
#define F2_A1 4608
#define F2_B0 9216
#define F2_B1 13824
#define F2_SMEM_BYTES (18432*4)
#define TP 132

__device__ __forceinline__ void f2_stage(unsigned* sm_u, int m0, int c, int buf, int tid)
{
    const int aoff = buf ? F2_A1 : 0;
    const int boff = buf ? F2_B1 : F2_B0;
#pragma unroll
    for (int j = 0; j < 4; j++) {
        const int i = tid + j * 256;
        const int row = i >> 3, u = i & 7;
        cp16(&sm_u[aoff + row * F2W + u * 4],
             &g_hb[(size_t)(m0 + row) * FFND + c * 64 + u * 8]);
        cp16(&sm_u[boff + row * F2W + u * 4],
             &g_w2tb[(size_t)row * FFND + c * 64 + u * 8]);
    }
    cp_commit();
}

__global__ __launch_bounds__(256, 2)
void k_ffn2_bf(const float* __restrict__ b2,
               const float* __restrict__ ln2g, const float* __restrict__ ln2b,
               float* __restrict__ out)
{
    extern __shared__ unsigned sm_u[];
    const int tid = threadIdx.x;
    const int warp = tid >> 5, lane = tid & 31;
    const int wm = warp >> 2, wn = warp & 3;
    const int g = lane >> 2, t = lane & 3;
    const int m0 = blockIdx.x * 128;

    float acc[4][4][4];
#pragma unroll
    for (int i = 0; i < 4; i++)
#pragma unroll
        for (int j = 0; j < 4; j++)
#pragma unroll
            for (int q = 0; q < 4; q++) acc[i][j][q] = 0.0f;

    f2_stage(sm_u, m0, 0, 0, tid);
    f2_stage(sm_u, m0, 1, 1, tid);
    cp_wait<1>();
    __syncthreads();

#pragma unroll 1
    for (int c = 0; c < 8; c++) {
        const unsigned* As = &sm_u[(c & 1) ? F2_A1 : 0];
        const unsigned* Bs = &sm_u[(c & 1) ? F2_B1 : F2_B0];
#pragma unroll
        for (int s = 0; s < 4; s++) {
            unsigned aw[4][4];
#pragma unroll
            for (int mf = 0; mf < 4; mf++) {
                const int row = wm * 64 + mf * 16 + g;
                aw[mf][0] = As[row * F2W + s * 8 + t];
                aw[mf][1] = As[(row + 8) * F2W + s * 8 + t];
                aw[mf][2] = As[row * F2W + s * 8 + t + 4];
                aw[mf][3] = As[(row + 8) * F2W + s * 8 + t + 4];
            }
#pragma unroll
            for (int nf = 0; nf < 4; nf++) {
                const int n = wn * 32 + nf * 8 + g;
                unsigned bw[2];
                bw[0] = Bs[n * F2W + s * 8 + t];
                bw[1] = Bs[n * F2W + s * 8 + t + 4];
#pragma unroll
                for (int mf = 0; mf < 4; mf++)
                    mma16(acc[mf][nf], aw[mf], bw);
            }
        }
        __syncthreads();
        if (c + 2 < 8) {
            f2_stage(sm_u, m0, c + 2, c & 1, tid);
            cp_wait<1>();
            __syncthreads();
        } else if (c + 1 < 8) {
            cp_wait<0>();
            __syncthreads();
        }
    }
    __syncthreads();

    float* T = (float*)sm_u;
#pragma unroll
    for (int nf = 0; nf < 4; nf++) {
        const int col = wn * 32 + nf * 8 + 2 * t;
        const float2 bb = *(const float2*)&b2[col];
#pragma unroll
        for (int mf = 0; mf < 4; mf++) {
            const int row0 = wm * 64 + mf * 16 + g;
            float2 o0, o1;
            o0.x = acc[mf][nf][0] + bb.x; o0.y = acc[mf][nf][1] + bb.y;
            o1.x = acc[mf][nf][2] + bb.x; o1.y = acc[mf][nf][3] + bb.y;
            *(float2*)&T[row0 * TP + col] = o0;
            *(float2*)&T[(row0 + 8) * TP + col] = o1;
        }
    }
    __syncthreads();

#pragma unroll
    for (int rr = 0; rr < 16; rr++) {
        const int row = warp * 16 + rr;
        const int r = m0 + row;
        const int c = lane * 4;
        float4 v = *(const float4*)&T[row * TP + c];
        float4 xv = *(const float4*)&g_x1[(size_t)r * CDIM + c];
        float v0 = v.x + xv.x, v1 = v.y + xv.y, v2 = v.z + xv.z, v3 = v.w + xv.w;
        float sum = v0 + v1 + v2 + v3;
        float sq  = v0 * v0 + v1 * v1 + v2 * v2 + v3 * v3;
#pragma unroll
        for (int off = 16; off > 0; off >>= 1) {
            sum += __shfl_xor_sync(0xffffffffu, sum, off);
            sq  += __shfl_xor_sync(0xffffffffu, sq,  off);
        }
        const float mu  = sum * (1.0f / 128.0f);
        const float var = sq * (1.0f / 128.0f) - mu * mu;
        const float wnr = rsqrtf(var + 1e-5f);
        float4 g4 = *(const float4*)&ln2g[c];
        float4 b4 = *(const float4*)&ln2b[c];
        float4 o;
        o.x = (v0 - mu) * wnr * g4.x + b4.x;
        o.y = (v1 - mu) * wnr * g4.y + b4.y;
        o.z = (v2 - mu) * wnr * g4.z + b4.z;
        o.w = (v3 - mu) * wnr * g4.w + b4.w;
        const int nn = r >> 5;
        const int ss = r & 31;
        *(float4*)&out[(size_t)ss * NLOC * CDIM + (size_t)nn * CDIM + c] = o;
    }
}

// ============================================================
extern "C" void kernel_launch(void* const* d_in, const int* in_sizes, int n_in,
                              void* d_out, int out_size)
{
    (void)in_sizes; (void)n_in; (void)out_size;
    const float* x    = (const float*)d_in[0];
    const float* wq   = (const float*)d_in[1];
    const float* bq   = (const float*)d_in[2];
    const float* wk   = (const float*)d_in[3];
    const float* bk   = (const float*)d_in[4];
    const float* wv   = (const float*)d_in[5];
    const float* bv   = (const float*)d_in[6];
    const float* ln1g = (const float*)d_in[7];
    const float* ln1b = (const float*)d_in[8];
    const float* w1   = (const float*)d_in[9];
    const float* b1   = (const float*)d_in[10];
    const float* w2   = (const float*)d_in[11];
    const float* b2   = (const float*)d_in[12];
    const float* ln2g = (const float*)d_in[13];
    const float* ln2b = (const float*)d_in[14];
    float* out = (float*)d_out;

    cudaFuncSetAttribute(k_fused_attn, cudaFuncAttributeMaxDynamicSharedMemorySize, M_SMEM_BYTES);
    cudaFuncSetAttribute(k_ffn1_bf, cudaFuncAttributeMaxDynamicSharedMemorySize, F1_SMEM_BYTES);
    cudaFuncSetAttribute(k_ffn2_bf, cudaFuncAttributeMaxDynamicSharedMemorySize, F2_SMEM_BYTES);

    dim3 tg(16, 16, 5), tb(32, 8);
    k_wtb<<<tg, tb>>>(w1, w2, wq, wk, wv);

    k_fused_attn<<<MROWS / 64, 256, M_SMEM_BYTES>>>(x, bq, bk, bv, ln1g, ln1b);

    k_ffn1_bf<<<MROWS / 128, 256, F1_SMEM_BYTES>>>(b1);

    k_ffn2_bf<<<MROWS / 128, 256, F2_SMEM_BYTES>>>(b2, ln2g, ln2b, out);
}

// round 12
// speedup vs baseline: 1.3587x; 1.0297x over previous
#include <cuda_runtime.h>
#include <cuda_bf16.h>
#include <math.h>

#define NLOC 8192
#define SEQ 32
#define CDIM 128
#define NHEAD 8
#define HD 16
#define MROWS (NLOC*SEQ)   // 262144
#define FFND 512

// -------- scratch (static device globals; no runtime allocation) --------
__device__ float g_x1[(size_t)MROWS * CDIM];            // fp32 residual
__device__ __nv_bfloat16 g_x1b[(size_t)MROWS * CDIM];   // ffn A operand
__device__ __nv_bfloat16 g_w1tb[(size_t)FFND * CDIM];   // w1^T bf16 [512][128]
__device__ __nv_bfloat16 g_w2tb[(size_t)CDIM * FFND];   // w2^T bf16 [128][512]
__device__ __nv_bfloat16 g_wqtb[(size_t)CDIM * CDIM];   // wq^T bf16 [n][k]
__device__ __nv_bfloat16 g_wktb[(size_t)CDIM * CDIM];
__device__ __nv_bfloat16 g_wvtb[(size_t)CDIM * CDIM];

// ======================= mma / cp.async helpers =======================
__device__ __forceinline__ void mma16(float* c, const unsigned* a, const unsigned* b) {
    asm volatile(
        "mma.sync.aligned.m16n8k16.row.col.f32.bf16.bf16.f32 "
        "{%0,%1,%2,%3}, {%4,%5,%6,%7}, {%8,%9}, {%0,%1,%2,%3};"
        : "+f"(c[0]), "+f"(c[1]), "+f"(c[2]), "+f"(c[3])
        : "r"(a[0]), "r"(a[1]), "r"(a[2]), "r"(a[3]),
          "r"(b[0]), "r"(b[1]));
}

__device__ __forceinline__ void cp16(void* s, const void* g) {
    unsigned saddr = (unsigned)__cvta_generic_to_shared(s);
    asm volatile("cp.async.cg.shared.global [%0], [%1], 16;" :: "r"(saddr), "l"(g));
}
__device__ __forceinline__ void cp_commit() {
    asm volatile("cp.async.commit_group;");
}
template<int N>
__device__ __forceinline__ void cp_wait() {
    asm volatile("cp.async.wait_group %0;" :: "n"(N));
}

// packed f32x2
typedef unsigned long long u64t;
__device__ __forceinline__ u64t pk2(float lo, float hi) {
    u64t r; asm("mov.b64 %0,{%1,%2};" : "=l"(r) : "f"(lo), "f"(hi)); return r;
}
__device__ __forceinline__ void upk2(u64t v, float& lo, float& hi) {
    asm("mov.b64 {%0,%1},%2;" : "=f"(lo), "=f"(hi) : "l"(v));
}
__device__ __forceinline__ void fma2(u64t& d, u64t a, u64t b) {
    asm("fma.rn.f32x2 %0,%1,%2,%0;" : "+l"(d) : "l"(a), "l"(b));
}

// ============================================================
// Kernel 0: transpose + convert all weights to bf16 (n-major)
// ============================================================
__global__ void k_wtb(const float* __restrict__ w1, const float* __restrict__ w2,
                      const float* __restrict__ wq, const float* __restrict__ wk,
                      const float* __restrict__ wv)
{
    __shared__ float t[32][33];
    const int which = blockIdx.z;
    const float* srcs[5] = { w1, w2, wq, wk, wv };
    __nv_bfloat16* dsts[5] = { g_w1tb, g_w2tb, g_wqtb, g_wktb, g_wvtb };
    const int Rs[5] = { 128, 512, 128, 128, 128 };
    const int Cs[5] = { 512, 128, 128, 128, 128 };
    const float* src = srcs[which];
    __nv_bfloat16* dst = dsts[which];
    const int R = Rs[which], C = Cs[which];
    const int r0 = blockIdx.y * 32, c0 = blockIdx.x * 32;
    if (r0 >= R || c0 >= C) return;
    const int lx = threadIdx.x, ly = threadIdx.y;
#pragma unroll
    for (int i = 0; i < 32; i += 8)
        t[ly + i][lx] = src[(size_t)(r0 + ly + i) * C + c0 + lx];
    __syncthreads();
#pragma unroll
    for (int i = 0; i < 32; i += 8)
        dst[(size_t)(c0 + ly + i) * R + r0 + lx] = __float2bfloat16(t[lx][ly + i]);
}

// ============================================================
// shared mma pass: OUT(64x128) warp-tiled 32x32 (warps 2x4)
// A: bf16 [64][128] pitch A_W words; B: bf16 n-major [128][128] pitch A_W
// ============================================================
#define A_W 68

__device__ __forceinline__ void f_mma_pass(const unsigned* __restrict__ As,
                                           const unsigned* __restrict__ Bs,
                                           float acc[2][4][4],
                                           int wm, int wn, int g, int t)
{
#pragma unroll
    for (int s = 0; s < 8; s++) {
        unsigned aw[2][4];
#pragma unroll
        for (int mf = 0; mf < 2; mf++) {
            const int row = wm * 32 + mf * 16 + g;
            aw[mf][0] = As[row * A_W + s * 8 + t];
            aw[mf][1] = As[(row + 8) * A_W + s * 8 + t];
            aw[mf][2] = As[row * A_W + s * 8 + t + 4];
            aw[mf][3] = As[(row + 8) * A_W + s * 8 + t + 4];
        }
#pragma unroll
        for (int nf = 0; nf < 4; nf++) {
            const int n = wn * 32 + nf * 8 + g;
            unsigned bw[2];
            bw[0] = Bs[n * A_W + s * 8 + t];
            bw[1] = Bs[n * A_W + s * 8 + t + 4];
#pragma unroll
            for (int mf = 0; mf < 2; mf++)
                mma16(acc[mf][nf], aw[mf], bw);
        }
    }
}

__device__ __forceinline__ void f_mma_pass2(const unsigned* __restrict__ As,
                                            const unsigned* __restrict__ Bs0,
                                            const unsigned* __restrict__ Bs1,
                                            float acc0[2][4][4], float acc1[2][4][4],
                                            int wm, int wn, int g, int t)
{
#pragma unroll
    for (int s = 0; s < 8; s++) {
        unsigned aw[2][4];
#pragma unroll
        for (int mf = 0; mf < 2; mf++) {
            const int row = wm * 32 + mf * 16 + g;
            aw[mf][0] = As[row * A_W + s * 8 + t];
            aw[mf][1] = As[(row + 8) * A_W + s * 8 + t];
            aw[mf][2] = As[row * A_W + s * 8 + t + 4];
            aw[mf][3] = As[(row + 8) * A_W + s * 8 + t + 4];
        }
#pragma unroll
        for (int nf = 0; nf < 4; nf++) {
            const int n = wn * 32 + nf * 8 + g;
            unsigned bw0[2], bw1[2];
            bw0[0] = Bs0[n * A_W + s * 8 + t];
            bw0[1] = Bs0[n * A_W + s * 8 + t + 4];
            bw1[0] = Bs1[n * A_W + s * 8 + t];
            bw1[1] = Bs1[n * A_W + s * 8 + t + 4];
#pragma unroll
            for (int mf = 0; mf < 2; mf++) {
                mma16(acc0[mf][nf], aw[mf], bw0);
                mma16(acc1[mf][nf], aw[mf], bw1);
            }
        }
    }
}

// ============================================================
// Kernel 1 (FUSED): bf16 QKV GEMM (two-pass) + rotary + attention
// + residual + LN1.   (unchanged from Round 11)
// ============================================================
#define FB0 4352
#define FB1 13056
#define M_SMEM_WORDS 25344
#define M_SMEM_BYTES (M_SMEM_WORDS*4)   // 101376 B
#define FP 132

__device__ __forceinline__ void f_stage_w(unsigned* sm_u, int dstoff,
                                          const __nv_bfloat16* W, int tid)
{
#pragma unroll
    for (int j = 0; j < 8; j++) {
        const int i = tid + j * 256;
        const int row = i >> 4, u = i & 15;
        cp16(&sm_u[dstoff + row * A_W + u * 4], &W[(size_t)row * CDIM + u * 8]);
    }
    cp_commit();
}

__global__ __launch_bounds__(256, 2)
void k_fused_attn(const float* __restrict__ x,
                  const float* __restrict__ bq, const float* __restrict__ bk,
                  const float* __restrict__ bv,
                  const float* __restrict__ ln1g, const float* __restrict__ ln1b)
{
    extern __shared__ unsigned sm_u[];
    float* smf = (float*)sm_u;
    __shared__ float sinT[SEQ][8];
    __shared__ float cosT[SEQ][8];

    float* Kbuf = smf;
    float* Vbuf = smf + 8448;
    float* Qbuf = smf + 16896;

    const int tid = threadIdx.x;
    const int warp = tid >> 5, lane = tid & 31;
    const int wm = warp >> 2, wn = warp & 3;
    const int g = lane >> 2, t = lane & 3;
    const int m0 = blockIdx.x * 64;

    if (tid < SEQ * 8) {
        const int s = tid >> 3, j = tid & 7;
        const float ang = powf(10000.0f, -(float)j / 7.0f);
        float sv, cv;
        sincosf((float)s * ang, &sv, &cv);
        sinT[s][j] = sv;
        cosT[s][j] = cv;
    }

    f_stage_w(sm_u, FB0, g_wktb, tid);
    f_stage_w(sm_u, FB1, g_wvtb, tid);
    {
        const int row = tid >> 2;
        const int seg = tid & 3;
        const int r = m0 + row;
        const float* src = &x[(size_t)(r & 31) * (NLOC * CDIM)
                              + (size_t)(r >> 5) * CDIM + seg * 32];
        unsigned* dstw = &sm_u[row * A_W + seg * 16];
#pragma unroll
        for (int q = 0; q < 8; q++) {
            float4 v = *(const float4*)(src + q * 4);
            __nv_bfloat162 b0 = __floats2bfloat162_rn(v.x, v.y);
            __nv_bfloat162 b1 = __floats2bfloat162_rn(v.z, v.w);
            dstw[q * 2]     = *(unsigned*)&b0;
            dstw[q * 2 + 1] = *(unsigned*)&b1;
        }
    }
    cp_wait<0>();
    __syncthreads();

    float acc[3][2][4][4];
#pragma unroll
    for (int w = 0; w < 3; w++)
#pragma unroll
        for (int i = 0; i < 2; i++)
#pragma unroll
            for (int j = 0; j < 4; j++)
#pragma unroll
                for (int q = 0; q < 4; q++) acc[w][i][j][q] = 0.0f;

    f_mma_pass2(sm_u, &sm_u[FB0], &sm_u[FB1], acc[0], acc[1], wm, wn, g, t);
    __syncthreads();

    f_stage_w(sm_u, FB0, g_wqtb, tid);
    cp_wait<0>();
    __syncthreads();
    f_mma_pass(sm_u, &sm_u[FB0], acc[2], wm, wn, g, t);
    __syncthreads();

    {
        const float* biases[3] = { bk, bv, bq };
        float* dsts[3] = { Kbuf, Vbuf, Qbuf };
#pragma unroll
        for (int w = 0; w < 3; w++) {
            float* dst = dsts[w];
            const float* BIAS = biases[w];
#pragma unroll
            for (int nf = 0; nf < 4; nf++) {
                const int col = wn * 32 + nf * 8 + 2 * t;
                const float2 bv2 = *(const float2*)&BIAS[col];
#pragma unroll
                for (int mf = 0; mf < 2; mf++) {
                    const int row0 = wm * 32 + mf * 16 + g;
                    float2 o0, o1;
                    o0.x = acc[w][mf][nf][0] + bv2.x; o0.y = acc[w][mf][nf][1] + bv2.y;
                    o1.x = acc[w][mf][nf][2] + bv2.x; o1.y = acc[w][mf][nf][3] + bv2.y;
                    *(float2*)&dst[row0 * FP + col] = o0;
                    *(float2*)&dst[(row0 + 8) * FP + col] = o1;
                }
            }
        }
    }
    __syncthreads();

#pragma unroll
    for (int task = tid; task < 64 * NHEAD; task += 256) {
        const int row = task >> 3, h = task & 7;
        const int s = row & 31;
        float tq[HD], tk[HD];
#pragma unroll
        for (int d4 = 0; d4 < 4; d4++) {
            *(float4*)&tq[d4 * 4] = *(const float4*)&Qbuf[row * FP + h * 16 + d4 * 4];
            *(float4*)&tk[d4 * 4] = *(const float4*)&Kbuf[row * FP + h * 16 + d4 * 4];
        }
        float rq[HD], rk[HD];
#pragma unroll
        for (int d = 0; d < HD; d++) {
            const float sv = sinT[s][d >> 1];
            const float cv = cosT[s][d >> 1];
            const int pc = (d < 8) ? (2 * d + 1) : (2 * d - 16);
            const float sgn = (d < 8) ? -1.0f : 1.0f;
            rq[d] = tq[d] * cv + sgn * tq[pc] * sv;
            rk[d] = tk[d] * cv + sgn * tk[pc] * sv;
        }
#pragma unroll
        for (int d4 = 0; d4 < 4; d4++) {
            *(float4*)&Qbuf[row * FP + h * 16 + d4 * 4] = *(const float4*)&rq[d4 * 4];
            *(float4*)&Kbuf[row * FP + h * 16 + d4 * 4] = *(const float4*)&rk[d4 * 4];
        }
    }
    __syncthreads();

    const int h = warp;
    const float decay = log1pf(-exp2f(-(1.0f + 3.0f * (float)h / 8.0f)));

#pragma unroll
    for (int l = 0; l < 2; l++) {
        const int qrow = l * 32 + lane;

        u64t q2[8];
        {
            const float* qp = &Qbuf[qrow * FP + h * 16];
            ulonglong2 qa = *(const ulonglong2*)(qp);
            ulonglong2 qb = *(const ulonglong2*)(qp + 4);
            ulonglong2 qc = *(const ulonglong2*)(qp + 8);
            ulonglong2 qd = *(const ulonglong2*)(qp + 12);
            q2[0] = qa.x; q2[1] = qa.y; q2[2] = qb.x; q2[3] = qb.y;
            q2[4] = qc.x; q2[5] = qc.y; q2[6] = qd.x; q2[7] = qd.y;
        }

        float p[SEQ];
        float mx = -1e30f;
#pragma unroll
        for (int j = 0; j < SEQ; j++) {
            const float* kp = &Kbuf[(l * 32 + j) * FP + h * 16];
            ulonglong2 ka = *(const ulonglong2*)(kp);
            ulonglong2 kb = *(const ulonglong2*)(kp + 4);
            ulonglong2 kc = *(const ulonglong2*)(kp + 8);
            ulonglong2 kd = *(const ulonglong2*)(kp + 12);
            u64t s2 = 0ull;
            fma2(s2, q2[0], ka.x); fma2(s2, q2[1], ka.y);
            fma2(s2, q2[2], kb.x); fma2(s2, q2[3], kb.y);
            fma2(s2, q2[4], kc.x); fma2(s2, q2[5], kc.y);
            fma2(s2, q2[6], kd.x); fma2(s2, q2[7], kd.y);
            float lo, hi;
            upk2(s2, lo, hi);
            const float dot = lo + hi + fabsf((float)(lane - j)) * decay;
            p[j] = dot;
            mx = fmaxf(mx, dot);
        }
        float sum = 0.0f;
#pragma unroll
        for (int j = 0; j < SEQ; j++) { p[j] = expf(p[j] - mx); sum += p[j]; }
        const float inv = 1.0f / sum;

        u64t o2[8];
#pragma unroll
        for (int i = 0; i < 8; i++) o2[i] = 0ull;
#pragma unroll
        for (int j = 0; j < SEQ; j++) {
            const float* vp = &Vbuf[(l * 32 + j) * FP + h * 16];
            ulonglong2 va = *(const ulonglong2*)(vp);
            ulonglong2 vb = *(const ulonglong2*)(vp + 4);
            ulonglong2 vc = *(const ulonglong2*)(vp + 8);
            ulonglong2 vd = *(const ulonglong2*)(vp + 12);
            const u64t pj2 = pk2(p[j], p[j]);
            fma2(o2[0], va.x, pj2); fma2(o2[1], va.y, pj2);
            fma2(o2[2], vb.x, pj2); fma2(o2[3], vb.y, pj2);
            fma2(o2[4], vc.x, pj2); fma2(o2[5], vc.y, pj2);
            fma2(o2[6], vd.x, pj2); fma2(o2[7], vd.y, pj2);
        }
        float o[HD];
#pragma unroll
        for (int i = 0; i < 8; i++) {
            float lo, hi;
            upk2(o2[i], lo, hi);
            o[2 * i] = lo * inv;
            o[2 * i + 1] = hi * inv;
        }
#pragma unroll
        for (int d4 = 0; d4 < 4; d4++)
            *(float4*)&Qbuf[qrow * FP + h * 16 + d4 * 4] = *(const float4*)&o[d4 * 4];
    }
    __syncthreads();

#pragma unroll
    for (int rr = 0; rr < 8; rr++) {
        const int row = warp * 8 + rr;
        const int r = m0 + row;
        const int c = lane * 4;
        float4 ov = *(const float4*)&Qbuf[row * FP + c];
        float4 xv = *(const float4*)&x[(size_t)(r & 31) * (NLOC * CDIM) + (size_t)(r >> 5) * CDIM + c];
        float v0 = ov.x + xv.x, v1 = ov.y + xv.y, v2 = ov.z + xv.z, v3 = ov.w + xv.w;
        float sum = v0 + v1 + v2 + v3;
        float sq  = v0 * v0 + v1 * v1 + v2 * v2 + v3 * v3;
#pragma unroll
        for (int off = 16; off > 0; off >>= 1) {
            sum += __shfl_xor_sync(0xffffffffu, sum, off);
            sq  += __shfl_xor_sync(0xffffffffu, sq,  off);
        }
        const float mu  = sum * (1.0f / 128.0f);
        const float var = sq * (1.0f / 128.0f) - mu * mu;
        const float wnr = rsqrtf(var + 1e-5f);
        float4 g4 = *(const float4*)&ln1g[c];
        float4 b4 = *(const float4*)&ln1b[c];
        float4 o;
        o.x = (v0 - mu) * wnr * g4.x + b4.x;
        o.y = (v1 - mu) * wnr * g4.y + b4.y;
        o.z = (v2 - mu) * wnr * g4.z + b4.z;
        o.w = (v3 - mu) * wnr * g4.w + b4.w;
        *(float4*)&g_x1[(size_t)r * CDIM + c] = o;
        __nv_bfloat162* bd = (__nv_bfloat162*)&g_x1b[(size_t)r * CDIM + c];
        bd[0] = __floats2bfloat162_rn(o.x, o.y);
        bd[1] = __floats2bfloat162_rn(o.z, o.w);
    }
}

// ============================================================
// Kernel 2 (FUSED FFN): out = LN2(relu(x1b@w1+b1)@w2 + b2 + x1)
// 256 thr / 8 warps (2x4), CTA = 64 rows, 2 CTAs/SM.
// H never leaves smem. smem words:
//   A  [64x128 bf16]  @0      (4352)
//   Hc [64x128 bf16]  @4352   (4352)
//   B1 [128x128 bf16] @8704   (8704)   w1 chunk (n-major)
//   B2 [128x128 bf16] @17408  (8704)   w2 chunk (n-major)
// total 26112 words = 104448 B; T epilogue (64x132 f32) overlays A+Hc.
// ============================================================
#define FF_HC 4352
#define FF_B1 8704
#define FF_B2 17408
#define FF_SMEM_WORDS 26112
#define FF_SMEM_BYTES (FF_SMEM_WORDS*4)
#define TP 132

__device__ __forceinline__ void ff_stage_w(unsigned* sm_u, int nt, int tid)
{
#pragma unroll
    for (int j = 0; j < 8; j++) {
        const int i = tid + j * 256;
        const int row = i >> 4, u = i & 15;
        cp16(&sm_u[FF_B1 + row * A_W + u * 4],
             &g_w1tb[(size_t)(nt * 128 + row) * CDIM + u * 8]);
        cp16(&sm_u[FF_B2 + row * A_W + u * 4],
             &g_w2tb[(size_t)row * FFND + nt * 128 + u * 8]);
    }
    cp_commit();
}

__global__ __launch_bounds__(256, 2)
void k_ffn_bf(const float* __restrict__ b1, const float* __restrict__ b2,
              const float* __restrict__ ln2g, const float* __restrict__ ln2b,
              float* __restrict__ out)
{
    extern __shared__ unsigned sm_u[];
    const int tid = threadIdx.x;
    const int warp = tid >> 5, lane = tid & 31;
    const int wm = warp >> 2, wn = warp & 3;
    const int g = lane >> 2, t = lane & 3;
    const int m0 = blockIdx.x * 64;

    // stage A (x1b 64x128) + weights for nt=0
#pragma unroll
    for (int j = 0; j < 4; j++) {
        const int i = tid + j * 256;
        const int row = i >> 4, u = i & 15;
        cp16(&sm_u[row * A_W + u * 4],
             &g_x1b[(size_t)(m0 + row) * CDIM + u * 8]);
    }
    ff_stage_w(sm_u, 0, tid);
    cp_wait<0>();
    __syncthreads();

    float acc2[2][4][4];
#pragma unroll
    for (int i = 0; i < 2; i++)
#pragma unroll
        for (int j = 0; j < 4; j++)
#pragma unroll
            for (int q = 0; q < 4; q++) acc2[i][j][q] = 0.0f;

#pragma unroll 1
    for (int nt = 0; nt < 4; nt++) {
        // ---- H chunk: accH = A @ w1_chunk ----
        float accH[2][4][4];
#pragma unroll
        for (int i = 0; i < 2; i++)
#pragma unroll
            for (int j = 0; j < 4; j++)
#pragma unroll
                for (int q = 0; q < 4; q++) accH[i][j][q] = 0.0f;
        f_mma_pass(sm_u, &sm_u[FF_B1], accH, wm, wn, g, t);

        // ---- bias + relu -> Hc (bf16, smem) ----
#pragma unroll
        for (int nf = 0; nf < 4; nf++) {
            const int col = wn * 32 + nf * 8 + 2 * t;
            const float2 bb = *(const float2*)&b1[nt * 128 + col];
#pragma unroll
            for (int mf = 0; mf < 2; mf++) {
                const int row0 = wm * 32 + mf * 16 + g;
                float h00 = fmaxf(accH[mf][nf][0] + bb.x, 0.0f);
                float h01 = fmaxf(accH[mf][nf][1] + bb.y, 0.0f);
                float h10 = fmaxf(accH[mf][nf][2] + bb.x, 0.0f);
                float h11 = fmaxf(accH[mf][nf][3] + bb.y, 0.0f);
                __nv_bfloat162 p0 = __floats2bfloat162_rn(h00, h01);
                __nv_bfloat162 p1 = __floats2bfloat162_rn(h10, h11);
                sm_u[FF_HC + row0 * A_W + (col >> 1)]       = *(unsigned*)&p0;
                sm_u[FF_HC + (row0 + 8) * A_W + (col >> 1)] = *(unsigned*)&p1;
            }
        }
        __syncthreads();   // Hc complete

        // ---- acc2 += Hc @ w2_chunk ----
        f_mma_pass(&sm_u[FF_HC], &sm_u[FF_B2], acc2, wm, wn, g, t);
        __syncthreads();   // all reads of B1/B2/Hc done

        if (nt < 3) {
            ff_stage_w(sm_u, nt + 1, tid);
            cp_wait<0>();
            __syncthreads();
        }
    }

    // ---- epilogue: acc2 + b2 -> T (f32, overlays A+Hc) ----
    float* T = (float*)sm_u;
#pragma unroll
    for (int nf = 0; nf < 4; nf++) {
        const int col = wn * 32 + nf * 8 + 2 * t;
        const float2 bb = *(const float2*)&b2[col];
#pragma unroll
        for (int mf = 0; mf < 2; mf++) {
            const int row0 = wm * 32 + mf * 16 + g;
            float2 o0, o1;
            o0.x = acc2[mf][nf][0] + bb.x; o0.y = acc2[mf][nf][1] + bb.y;
            o1.x = acc2[mf][nf][2] + bb.x; o1.y = acc2[mf][nf][3] + bb.y;
            *(float2*)&T[row0 * TP + col] = o0;
            *(float2*)&T[(row0 + 8) * TP + col] = o1;
        }
    }
    __syncthreads();

    // ---- residual + LN2 + transposed store ----
#pragma unroll
    for (int rr = 0; rr < 8; rr++) {
        const int row = warp * 8 + rr;
        const int r = m0 + row;
        const int c = lane * 4;
        float4 v = *(const float4*)&T[row * TP + c];
        float4 xv = *(const float4*)&g_x1[(size_t)r * CDIM + c];
        float v0 = v.x + xv.x, v1 = v.y + xv.y, v2 = v.z + xv.z, v3 = v.w + xv.w;
        float sum = v0 + v1 + v2 + v3;
        float sq  = v0 * v0 + v1 * v1 + v2 * v2 + v3 * v3;
#pragma unroll
        for (int off = 16; off > 0; off >>= 1) {
            sum += __shfl_xor_sync(0xffffffffu, sum, off);
            sq  += __shfl_xor_sync(0xffffffffu, sq,  off);
        }
        const float mu  = sum * (1.0f / 128.0f);
        const float var = sq * (1.0f / 128.0f) - mu * mu;
        const float wnr = rsqrtf(var + 1e-5f);
        float4 g4 = *(const float4*)&ln2g[c];
        float4 b4 = *(const float4*)&ln2b[c];
        float4 o;
        o.x = (v0 - mu) * wnr * g4.x + b4.x;
        o.y = (v1 - mu) * wnr * g4.y + b4.y;
        o.z = (v2 - mu) * wnr * g4.z + b4.z;
        o.w = (v3 - mu) * wnr * g4.w + b4.w;
        const int nn = r >> 5;
        const int ss = r & 31;
        *(float4*)&out[(size_t)ss * NLOC * CDIM + (size_t)nn * CDIM + c] = o;
    }
}

// ============================================================
extern "C" void kernel_launch(void* const* d_in, const int* in_sizes, int n_in,
                              void* d_out, int out_size)
{
    (void)in_sizes; (void)n_in; (void)out_size;
    const float* x    = (const float*)d_in[0];
    const float* wq   = (const float*)d_in[1];
    const float* bq   = (const float*)d_in[2];
    const float* wk   = (const float*)d_in[3];
    const float* bk   = (const float*)d_in[4];
    const float* wv   = (const float*)d_in[5];
    const float* bv   = (const float*)d_in[6];
    const float* ln1g = (const float*)d_in[7];
    const float* ln1b = (const float*)d_in[8];
    const float* w1   = (const float*)d_in[9];
    const float* b1   = (const float*)d_in[10];
    const float* w2   = (const float*)d_in[11];
    const float* b2   = (const float*)d_in[12];
    const float* ln2g = (const float*)d_in[13];
    const float* ln2b = (const float*)d_in[14];
    float* out = (float*)d_out;

    cudaFuncSetAttribute(k_fused_attn, cudaFuncAttributeMaxDynamicSharedMemorySize, M_SMEM_BYTES);
    cudaFuncSetAttribute(k_ffn_bf, cudaFuncAttributeMaxDynamicSharedMemorySize, FF_SMEM_BYTES);

    dim3 tg(16, 16, 5), tb(32, 8);
    k_wtb<<<tg, tb>>>(w1, w2, wq, wk, wv);

    k_fused_attn<<<MROWS / 64, 256, M_SMEM_BYTES>>>(x, bq, bk, bv, ln1g, ln1b);

    k_ffn_bf<<<MROWS / 64, 256, FF_SMEM_BYTES>>>(b1, b2, ln2g, ln2b, out);
}

// round 13
// speedup vs baseline: 1.4327x; 1.0545x over previous
#include <cuda_runtime.h>
#include <cuda_bf16.h>
#include <math.h>

#define NLOC 8192
#define SEQ 32
#define CDIM 128
#define NHEAD 8
#define HD 16
#define MROWS (NLOC*SEQ)   // 262144
#define FFND 512

// -------- weights (bf16, n-major) --------
__device__ __nv_bfloat16 g_w1tb[(size_t)FFND * CDIM];   // w1^T [512][128]
__device__ __nv_bfloat16 g_w2tb[(size_t)CDIM * FFND];   // w2^T [128][512]
__device__ __nv_bfloat16 g_wqtb[(size_t)CDIM * CDIM];
__device__ __nv_bfloat16 g_wktb[(size_t)CDIM * CDIM];
__device__ __nv_bfloat16 g_wvtb[(size_t)CDIM * CDIM];

// ======================= mma / cp.async helpers =======================
__device__ __forceinline__ void mma16(float* c, const unsigned* a, const unsigned* b) {
    asm volatile(
        "mma.sync.aligned.m16n8k16.row.col.f32.bf16.bf16.f32 "
        "{%0,%1,%2,%3}, {%4,%5,%6,%7}, {%8,%9}, {%0,%1,%2,%3};"
        : "+f"(c[0]), "+f"(c[1]), "+f"(c[2]), "+f"(c[3])
        : "r"(a[0]), "r"(a[1]), "r"(a[2]), "r"(a[3]),
          "r"(b[0]), "r"(b[1]));
}

__device__ __forceinline__ void cp16(void* s, const void* g) {
    unsigned saddr = (unsigned)__cvta_generic_to_shared(s);
    asm volatile("cp.async.cg.shared.global [%0], [%1], 16;" :: "r"(saddr), "l"(g));
}
__device__ __forceinline__ void cp_commit() {
    asm volatile("cp.async.commit_group;");
}
template<int N>
__device__ __forceinline__ void cp_wait() {
    asm volatile("cp.async.wait_group %0;" :: "n"(N));
}

typedef unsigned long long u64t;
__device__ __forceinline__ u64t pk2(float lo, float hi) {
    u64t r; asm("mov.b64 %0,{%1,%2};" : "=l"(r) : "f"(lo), "f"(hi)); return r;
}
__device__ __forceinline__ void upk2(u64t v, float& lo, float& hi) {
    asm("mov.b64 {%0,%1},%2;" : "=f"(lo), "=f"(hi) : "l"(v));
}
__device__ __forceinline__ void fma2(u64t& d, u64t a, u64t b) {
    asm("fma.rn.f32x2 %0,%1,%2,%0;" : "+l"(d) : "l"(a), "l"(b));
}

// ============================================================
// Kernel 0: transpose + convert all weights to bf16 (n-major)
// ============================================================
__global__ void k_wtb(const float* __restrict__ w1, const float* __restrict__ w2,
                      const float* __restrict__ wq, const float* __restrict__ wk,
                      const float* __restrict__ wv)
{
    __shared__ float t[32][33];
    const int which = blockIdx.z;
    const float* srcs[5] = { w1, w2, wq, wk, wv };
    __nv_bfloat16* dsts[5] = { g_w1tb, g_w2tb, g_wqtb, g_wktb, g_wvtb };
    const int Rs[5] = { 128, 512, 128, 128, 128 };
    const int Cs[5] = { 512, 128, 128, 128, 128 };
    const float* src = srcs[which];
    __nv_bfloat16* dst = dsts[which];
    const int R = Rs[which], C = Cs[which];
    const int r0 = blockIdx.y * 32, c0 = blockIdx.x * 32;
    if (r0 >= R || c0 >= C) return;
    const int lx = threadIdx.x, ly = threadIdx.y;
#pragma unroll
    for (int i = 0; i < 32; i += 8)
        t[ly + i][lx] = src[(size_t)(r0 + ly + i) * C + c0 + lx];
    __syncthreads();
#pragma unroll
    for (int i = 0; i < 32; i += 8)
        dst[(size_t)(c0 + ly + i) * R + r0 + lx] = __float2bfloat16(t[lx][ly + i]);
}

// ============================================================
// mma pass: OUT(64x128) warp-tiled 32x32 (warps 2x4)
// A bf16 [64][128] pitch A_W words; B bf16 n-major [128][128] pitch A_W
// ============================================================
#define A_W 68

__device__ __forceinline__ void f_mma_pass(const unsigned* __restrict__ As,
                                           const unsigned* __restrict__ Bs,
                                           float acc[2][4][4],
                                           int wm, int wn, int g, int t)
{
#pragma unroll
    for (int s = 0; s < 8; s++) {
        unsigned aw[2][4];
#pragma unroll
        for (int mf = 0; mf < 2; mf++) {
            const int row = wm * 32 + mf * 16 + g;
            aw[mf][0] = As[row * A_W + s * 8 + t];
            aw[mf][1] = As[(row + 8) * A_W + s * 8 + t];
            aw[mf][2] = As[row * A_W + s * 8 + t + 4];
            aw[mf][3] = As[(row + 8) * A_W + s * 8 + t + 4];
        }
#pragma unroll
        for (int nf = 0; nf < 4; nf++) {
            const int n = wn * 32 + nf * 8 + g;
            unsigned bw[2];
            bw[0] = Bs[n * A_W + s * 8 + t];
            bw[1] = Bs[n * A_W + s * 8 + t + 4];
#pragma unroll
            for (int mf = 0; mf < 2; mf++)
                mma16(acc[mf][nf], aw[mf], bw);
        }
    }
}

__device__ __forceinline__ void f_mma_pass2(const unsigned* __restrict__ As,
                                            const unsigned* __restrict__ Bs0,
                                            const unsigned* __restrict__ Bs1,
                                            float acc0[2][4][4], float acc1[2][4][4],
                                            int wm, int wn, int g, int t)
{
#pragma unroll
    for (int s = 0; s < 8; s++) {
        unsigned aw[2][4];
#pragma unroll
        for (int mf = 0; mf < 2; mf++) {
            const int row = wm * 32 + mf * 16 + g;
            aw[mf][0] = As[row * A_W + s * 8 + t];
            aw[mf][1] = As[(row + 8) * A_W + s * 8 + t];
            aw[mf][2] = As[row * A_W + s * 8 + t + 4];
            aw[mf][3] = As[(row + 8) * A_W + s * 8 + t + 4];
        }
#pragma unroll
        for (int nf = 0; nf < 4; nf++) {
            const int n = wn * 32 + nf * 8 + g;
            unsigned bw0[2], bw1[2];
            bw0[0] = Bs0[n * A_W + s * 8 + t];
            bw0[1] = Bs0[n * A_W + s * 8 + t + 4];
            bw1[0] = Bs1[n * A_W + s * 8 + t];
            bw1[1] = Bs1[n * A_W + s * 8 + t + 4];
#pragma unroll
            for (int mf = 0; mf < 2; mf++) {
                mma16(acc0[mf][nf], aw[mf], bw0);
                mma16(acc1[mf][nf], aw[mf], bw1);
            }
        }
    }
}

// ============================================================
// MEGA KERNEL: QKV + rotary + attention + LN1 + FFN1 + FFN2 + LN2
// 256 thr / 8 warps (2x4), CTA = 64 rows = 2 locations, 2 CTAs/SM.
//
// smem layout (words):
//  QKV phase:   A 4352 @0 | Bk 8704 @4352 | Bv 8704 @13056     (21760)
//  Attn phase:  Kbuf f32 8448 @0 | Vbuf 8448 @8448 | Qbuf 8448 @16896
//  FFN phase:   x1f f32 8448 @0 | Ab 4352 @8448 | Hc 4352 @12800 | B 8704 @17152
//  Epilogue:    T f32 8448 @8448 (over Ab+Hc), x1f @0 alive
//  total 25856 words = 103424 B  -> 2 CTAs/SM
// ============================================================
#define FB0 4352
#define FB1 13056
#define MG_X1F 0
#define MG_A   8448
#define MG_HC  12800
#define MG_B   17152
#define MG_WORDS 25856
#define MG_BYTES (MG_WORDS*4)
#define FP 132

__device__ __forceinline__ void f_stage_w(unsigned* sm_u, int dstoff,
                                          const __nv_bfloat16* W, int tid)
{
#pragma unroll
    for (int j = 0; j < 8; j++) {
        const int i = tid + j * 256;
        const int row = i >> 4, u = i & 15;
        cp16(&sm_u[dstoff + row * A_W + u * 4], &W[(size_t)row * CDIM + u * 8]);
    }
    cp_commit();
}

__global__ __launch_bounds__(256, 2)
void k_block(const float* __restrict__ x,
             const float* __restrict__ bq, const float* __restrict__ bk,
             const float* __restrict__ bv,
             const float* __restrict__ ln1g, const float* __restrict__ ln1b,
             const float* __restrict__ b1, const float* __restrict__ b2,
             const float* __restrict__ ln2g, const float* __restrict__ ln2b,
             float* __restrict__ out)
{
    extern __shared__ unsigned sm_u[];
    float* smf = (float*)sm_u;
    __shared__ float sinT[SEQ][8];
    __shared__ float cosT[SEQ][8];

    float* Kbuf = smf;
    float* Vbuf = smf + 8448;
    float* Qbuf = smf + 16896;

    const int tid = threadIdx.x;
    const int warp = tid >> 5, lane = tid & 31;
    const int wm = warp >> 2, wn = warp & 3;
    const int g = lane >> 2, t = lane & 3;
    const int m0 = blockIdx.x * 64;

    if (tid < SEQ * 8) {
        const int s = tid >> 3, j = tid & 7;
        const float ang = powf(10000.0f, -(float)j / 7.0f);
        float sv, cv;
        sincosf((float)s * ang, &sv, &cv);
        sinT[s][j] = sv;
        cosT[s][j] = cv;
    }

    // ================= Phase 1: QKV GEMM =================
    f_stage_w(sm_u, FB0, g_wktb, tid);
    f_stage_w(sm_u, FB1, g_wvtb, tid);
    {
        const int row = tid >> 2;
        const int seg = tid & 3;
        const int r = m0 + row;
        const float* src = &x[(size_t)(r & 31) * (NLOC * CDIM)
                              + (size_t)(r >> 5) * CDIM + seg * 32];
        unsigned* dstw = &sm_u[row * A_W + seg * 16];
#pragma unroll
        for (int q = 0; q < 8; q++) {
            float4 v = *(const float4*)(src + q * 4);
            __nv_bfloat162 b0 = __floats2bfloat162_rn(v.x, v.y);
            __nv_bfloat162 b1c = __floats2bfloat162_rn(v.z, v.w);
            dstw[q * 2]     = *(unsigned*)&b0;
            dstw[q * 2 + 1] = *(unsigned*)&b1c;
        }
    }
    cp_wait<0>();
    __syncthreads();

    float acc[3][2][4][4];
#pragma unroll
    for (int w = 0; w < 3; w++)
#pragma unroll
        for (int i = 0; i < 2; i++)
#pragma unroll
            for (int j = 0; j < 4; j++)
#pragma unroll
                for (int q = 0; q < 4; q++) acc[w][i][j][q] = 0.0f;

    f_mma_pass2(sm_u, &sm_u[FB0], &sm_u[FB1], acc[0], acc[1], wm, wn, g, t);
    __syncthreads();

    f_stage_w(sm_u, FB0, g_wqtb, tid);
    cp_wait<0>();
    __syncthreads();
    f_mma_pass(sm_u, &sm_u[FB0], acc[2], wm, wn, g, t);
    __syncthreads();

    // epilogue: acc + bias -> K/V/Q fp32 tiles
    {
        const float* biases[3] = { bk, bv, bq };
        float* dsts[3] = { Kbuf, Vbuf, Qbuf };
#pragma unroll
        for (int w = 0; w < 3; w++) {
            float* dst = dsts[w];
            const float* BIAS = biases[w];
#pragma unroll
            for (int nf = 0; nf < 4; nf++) {
                const int col = wn * 32 + nf * 8 + 2 * t;
                const float2 bv2 = *(const float2*)&BIAS[col];
#pragma unroll
                for (int mf = 0; mf < 2; mf++) {
                    const int row0 = wm * 32 + mf * 16 + g;
                    float2 o0, o1;
                    o0.x = acc[w][mf][nf][0] + bv2.x; o0.y = acc[w][mf][nf][1] + bv2.y;
                    o1.x = acc[w][mf][nf][2] + bv2.x; o1.y = acc[w][mf][nf][3] + bv2.y;
                    *(float2*)&dst[row0 * FP + col] = o0;
                    *(float2*)&dst[(row0 + 8) * FP + col] = o1;
                }
            }
        }
    }
    __syncthreads();

    // ================= Phase 2: rotary + attention =================
#pragma unroll
    for (int task = tid; task < 64 * NHEAD; task += 256) {
        const int row = task >> 3, h = task & 7;
        const int s = row & 31;
        float tq[HD], tk[HD];
#pragma unroll
        for (int d4 = 0; d4 < 4; d4++) {
            *(float4*)&tq[d4 * 4] = *(const float4*)&Qbuf[row * FP + h * 16 + d4 * 4];
            *(float4*)&tk[d4 * 4] = *(const float4*)&Kbuf[row * FP + h * 16 + d4 * 4];
        }
        float rq[HD], rk[HD];
#pragma unroll
        for (int d = 0; d < HD; d++) {
            const float sv = sinT[s][d >> 1];
            const float cv = cosT[s][d >> 1];
            const int pc = (d < 8) ? (2 * d + 1) : (2 * d - 16);
            const float sgn = (d < 8) ? -1.0f : 1.0f;
            rq[d] = tq[d] * cv + sgn * tq[pc] * sv;
            rk[d] = tk[d] * cv + sgn * tk[pc] * sv;
        }
#pragma unroll
        for (int d4 = 0; d4 < 4; d4++) {
            *(float4*)&Qbuf[row * FP + h * 16 + d4 * 4] = *(const float4*)&rq[d4 * 4];
            *(float4*)&Kbuf[row * FP + h * 16 + d4 * 4] = *(const float4*)&rk[d4 * 4];
        }
    }
    __syncthreads();

    const int h = warp;
    const float decay = log1pf(-exp2f(-(1.0f + 3.0f * (float)h / 8.0f)));

#pragma unroll
    for (int l = 0; l < 2; l++) {
        const int qrow = l * 32 + lane;

        u64t q2[8];
        {
            const float* qp = &Qbuf[qrow * FP + h * 16];
            ulonglong2 qa = *(const ulonglong2*)(qp);
            ulonglong2 qb = *(const ulonglong2*)(qp + 4);
            ulonglong2 qc = *(const ulonglong2*)(qp + 8);
            ulonglong2 qd = *(const ulonglong2*)(qp + 12);
            q2[0] = qa.x; q2[1] = qa.y; q2[2] = qb.x; q2[3] = qb.y;
            q2[4] = qc.x; q2[5] = qc.y; q2[6] = qd.x; q2[7] = qd.y;
        }

        float p[SEQ];
        float mx = -1e30f;
#pragma unroll
        for (int j = 0; j < SEQ; j++) {
            const float* kp = &Kbuf[(l * 32 + j) * FP + h * 16];
            ulonglong2 ka = *(const ulonglong2*)(kp);
            ulonglong2 kb = *(const ulonglong2*)(kp + 4);
            ulonglong2 kc = *(const ulonglong2*)(kp + 8);
            ulonglong2 kd = *(const ulonglong2*)(kp + 12);
            u64t s2 = 0ull;
            fma2(s2, q2[0], ka.x); fma2(s2, q2[1], ka.y);
            fma2(s2, q2[2], kb.x); fma2(s2, q2[3], kb.y);
            fma2(s2, q2[4], kc.x); fma2(s2, q2[5], kc.y);
            fma2(s2, q2[6], kd.x); fma2(s2, q2[7], kd.y);
            float lo, hi;
            upk2(s2, lo, hi);
            const float dot = lo + hi + fabsf((float)(lane - j)) * decay;
            p[j] = dot;
            mx = fmaxf(mx, dot);
        }
        float sum = 0.0f;
#pragma unroll
        for (int j = 0; j < SEQ; j++) { p[j] = expf(p[j] - mx); sum += p[j]; }
        const float inv = 1.0f / sum;

        u64t o2[8];
#pragma unroll
        for (int i = 0; i < 8; i++) o2[i] = 0ull;
#pragma unroll
        for (int j = 0; j < SEQ; j++) {
            const float* vp = &Vbuf[(l * 32 + j) * FP + h * 16];
            ulonglong2 va = *(const ulonglong2*)(vp);
            ulonglong2 vb = *(const ulonglong2*)(vp + 4);
            ulonglong2 vc = *(const ulonglong2*)(vp + 8);
            ulonglong2 vd = *(const ulonglong2*)(vp + 12);
            const u64t pj2 = pk2(p[j], p[j]);
            fma2(o2[0], va.x, pj2); fma2(o2[1], va.y, pj2);
            fma2(o2[2], vb.x, pj2); fma2(o2[3], vb.y, pj2);
            fma2(o2[4], vc.x, pj2); fma2(o2[5], vc.y, pj2);
            fma2(o2[6], vd.x, pj2); fma2(o2[7], vd.y, pj2);
        }
        float o[HD];
#pragma unroll
        for (int i = 0; i < 8; i++) {
            float lo, hi;
            upk2(o2[i], lo, hi);
            o[2 * i] = lo * inv;
            o[2 * i + 1] = hi * inv;
        }
#pragma unroll
        for (int d4 = 0; d4 < 4; d4++)
            *(float4*)&Qbuf[qrow * FP + h * 16 + d4 * 4] = *(const float4*)&o[d4 * 4];
    }
    __syncthreads();

    // ================= Phase 3: residual + LN1 -> smem x1 (f32 + bf16) =================
#pragma unroll
    for (int rr = 0; rr < 8; rr++) {
        const int row = warp * 8 + rr;
        const int r = m0 + row;
        const int c = lane * 4;
        float4 ov = *(const float4*)&Qbuf[row * FP + c];
        float4 xv = *(const float4*)&x[(size_t)(r & 31) * (NLOC * CDIM) + (size_t)(r >> 5) * CDIM + c];
        float v0 = ov.x + xv.x, v1 = ov.y + xv.y, v2 = ov.z + xv.z, v3 = ov.w + xv.w;
        float sum = v0 + v1 + v2 + v3;
        float sq  = v0 * v0 + v1 * v1 + v2 * v2 + v3 * v3;
#pragma unroll
        for (int off = 16; off > 0; off >>= 1) {
            sum += __shfl_xor_sync(0xffffffffu, sum, off);
            sq  += __shfl_xor_sync(0xffffffffu, sq,  off);
        }
        const float mu  = sum * (1.0f / 128.0f);
        const float var = sq * (1.0f / 128.0f) - mu * mu;
        const float wnr = rsqrtf(var + 1e-5f);
        float4 g4 = *(const float4*)&ln1g[c];
        float4 b4 = *(const float4*)&ln1b[c];
        float4 o;
        o.x = (v0 - mu) * wnr * g4.x + b4.x;
        o.y = (v1 - mu) * wnr * g4.y + b4.y;
        o.z = (v2 - mu) * wnr * g4.z + b4.z;
        o.w = (v3 - mu) * wnr * g4.w + b4.w;
        // x1 fp32 -> @MG_X1F (Kbuf region, dead)
        *(float4*)&smf[MG_X1F + row * FP + c] = o;
        // x1 bf16 -> @MG_A (Vbuf region, dead)
        __nv_bfloat162 p0 = __floats2bfloat162_rn(o.x, o.y);
        __nv_bfloat162 p1 = __floats2bfloat162_rn(o.z, o.w);
        sm_u[MG_A + row * A_W + (c >> 1)]     = *(unsigned*)&p0;
        sm_u[MG_A + row * A_W + (c >> 1) + 1] = *(unsigned*)&p1;
    }
    __syncthreads();   // x1f/x1b complete; Qbuf now dead -> B slot usable

    // ================= Phase 4: FFN (H in smem, single B slot) =================
    float acc2[2][4][4];
#pragma unroll
    for (int i = 0; i < 2; i++)
#pragma unroll
        for (int j = 0; j < 4; j++)
#pragma unroll
            for (int q = 0; q < 4; q++) acc2[i][j][q] = 0.0f;

#pragma unroll 1
    for (int nt = 0; nt < 4; nt++) {
        // stage w1 chunk into B
#pragma unroll
        for (int j = 0; j < 8; j++) {
            const int i = tid + j * 256;
            const int row = i >> 4, u = i & 15;
            cp16(&sm_u[MG_B + row * A_W + u * 4],
                 &g_w1tb[(size_t)(nt * 128 + row) * CDIM + u * 8]);
        }
        cp_commit();
        cp_wait<0>();
        __syncthreads();

        // accH = x1b @ w1_chunk
        float accH[2][4][4];
#pragma unroll
        for (int i = 0; i < 2; i++)
#pragma unroll
            for (int j = 0; j < 4; j++)
#pragma unroll
                for (int q = 0; q < 4; q++) accH[i][j][q] = 0.0f;
        f_mma_pass(&sm_u[MG_A], &sm_u[MG_B], accH, wm, wn, g, t);

        // bias + relu -> Hc (bf16)
#pragma unroll
        for (int nf = 0; nf < 4; nf++) {
            const int col = wn * 32 + nf * 8 + 2 * t;
            const float2 bb = *(const float2*)&b1[nt * 128 + col];
#pragma unroll
            for (int mf = 0; mf < 2; mf++) {
                const int row0 = wm * 32 + mf * 16 + g;
                float h00 = fmaxf(accH[mf][nf][0] + bb.x, 0.0f);
                float h01 = fmaxf(accH[mf][nf][1] + bb.y, 0.0f);
                float h10 = fmaxf(accH[mf][nf][2] + bb.x, 0.0f);
                float h11 = fmaxf(accH[mf][nf][3] + bb.y, 0.0f);
                __nv_bfloat162 p0 = __floats2bfloat162_rn(h00, h01);
                __nv_bfloat162 p1 = __floats2bfloat162_rn(h10, h11);
                sm_u[MG_HC + row0 * A_W + (col >> 1)]       = *(unsigned*)&p0;
                sm_u[MG_HC + (row0 + 8) * A_W + (col >> 1)] = *(unsigned*)&p1;
            }
        }
        __syncthreads();   // Hc visible; w1 reads of B done

        // stage w2 chunk into B (same slot)
#pragma unroll
        for (int j = 0; j < 8; j++) {
            const int i = tid + j * 256;
            const int row = i >> 4, u = i & 15;
            cp16(&sm_u[MG_B + row * A_W + u * 4],
                 &g_w2tb[(size_t)row * FFND + nt * 128 + u * 8]);
        }
        cp_commit();
        cp_wait<0>();
        __syncthreads();

        // acc2 += Hc @ w2_chunk
        f_mma_pass(&sm_u[MG_HC], &sm_u[MG_B], acc2, wm, wn, g, t);
        __syncthreads();   // B reads done before next overwrite
    }

    // ================= Phase 5: epilogue (bias + residual + LN2 + store) =================
    float* T = smf + MG_A;   // overlays Ab+Hc (dead); x1f @0 alive
#pragma unroll
    for (int nf = 0; nf < 4; nf++) {
        const int col = wn * 32 + nf * 8 + 2 * t;
        const float2 bb = *(const float2*)&b2[col];
#pragma unroll
        for (int mf = 0; mf < 2; mf++) {
            const int row0 = wm * 32 + mf * 16 + g;
            float2 o0, o1;
            o0.x = acc2[mf][nf][0] + bb.x; o0.y = acc2[mf][nf][1] + bb.y;
            o1.x = acc2[mf][nf][2] + bb.x; o1.y = acc2[mf][nf][3] + bb.y;
            *(float2*)&T[row0 * FP + col] = o0;
            *(float2*)&T[(row0 + 8) * FP + col] = o1;
        }
    }
    __syncthreads();

#pragma unroll
    for (int rr = 0; rr < 8; rr++) {
        const int row = warp * 8 + rr;
        const int r = m0 + row;
        const int c = lane * 4;
        float4 v = *(const float4*)&T[row * FP + c];
        float4 xv = *(const float4*)&smf[MG_X1F + row * FP + c];
        float v0 = v.x + xv.x, v1 = v.y + xv.y, v2 = v.z + xv.z, v3 = v.w + xv.w;
        float sum = v0 + v1 + v2 + v3;
        float sq  = v0 * v0 + v1 * v1 + v2 * v2 + v3 * v3;
#pragma unroll
        for (int off = 16; off > 0; off >>= 1) {
            sum += __shfl_xor_sync(0xffffffffu, sum, off);
            sq  += __shfl_xor_sync(0xffffffffu, sq,  off);
        }
        const float mu  = sum * (1.0f / 128.0f);
        const float var = sq * (1.0f / 128.0f) - mu * mu;
        const float wnr = rsqrtf(var + 1e-5f);
        float4 g4 = *(const float4*)&ln2g[c];
        float4 b4 = *(const float4*)&ln2b[c];
        float4 o;
        o.x = (v0 - mu) * wnr * g4.x + b4.x;
        o.y = (v1 - mu) * wnr * g4.y + b4.y;
        o.z = (v2 - mu) * wnr * g4.z + b4.z;
        o.w = (v3 - mu) * wnr * g4.w + b4.w;
        const int nn = r >> 5;
        const int ss = r & 31;
        *(float4*)&out[(size_t)ss * NLOC * CDIM + (size_t)nn * CDIM + c] = o;
    }
}

// ============================================================
extern "C" void kernel_launch(void* const* d_in, const int* in_sizes, int n_in,
                              void* d_out, int out_size)
{
    (void)in_sizes; (void)n_in; (void)out_size;
    const float* x    = (const float*)d_in[0];
    const float* wq   = (const float*)d_in[1];
    const float* bq   = (const float*)d_in[2];
    const float* wk   = (const float*)d_in[3];
    const float* bk   = (const float*)d_in[4];
    const float* wv   = (const float*)d_in[5];
    const float* bv   = (const float*)d_in[6];
    const float* ln1g = (const float*)d_in[7];
    const float* ln1b = (const float*)d_in[8];
    const float* w1   = (const float*)d_in[9];
    const float* b1   = (const float*)d_in[10];
    const float* w2   = (const float*)d_in[11];
    const float* b2   = (const float*)d_in[12];
    const float* ln2g = (const float*)d_in[13];
    const float* ln2b = (const float*)d_in[14];
    float* out = (float*)d_out;

    cudaFuncSetAttribute(k_block, cudaFuncAttributeMaxDynamicSharedMemorySize, MG_BYTES);

    dim3 tg(16, 16, 5), tb(32, 8);
    k_wtb<<<tg, tb>>>(w1, w2, wq, wk, wv);

    k_block<<<MROWS / 64, 256, MG_BYTES>>>(x, bq, bk, bv, ln1g, ln1b,
                                           b1, b2, ln2g, ln2b, out);
}